// round 1
// baseline (speedup 1.0000x reference)
#include <cuda_runtime.h>

#define N_TOK 32768
#define DIM   256
#define NCODE 1024

// d_out layout (float32, tuple order): z_q_st, loss, indices, new_cluster_size,
// new_embedding_avg, new_embedding
#define OFF_ZQ   0
#define OFF_LOSS (N_TOK * DIM)                 // 8388608
#define OFF_IDX  (OFF_LOSS + 1)                // 8388609
#define OFF_CS   (OFF_IDX + N_TOK)             // 8421377
#define OFF_AVG  (OFF_CS + NCODE)              // 8422401
#define OFF_EMB  (OFF_AVG + NCODE * DIM)       // 8684545

__device__ __align__(16) float g_enorm[NCODE];
__device__ float g_counts[NCODE];
__device__ float g_esum[NCODE * DIM];
__device__ float g_loss;
__device__ float g_nsum;

// ---------------------------------------------------------------------------
// packed f32x2 helpers (sm_100+ packed FFMA — 2 FMA per instruction)
// ---------------------------------------------------------------------------
__device__ __forceinline__ unsigned long long pack2(float lo, float hi) {
    unsigned long long r;
    asm("mov.b64 %0, {%1, %2};" : "=l"(r) : "f"(lo), "f"(hi));
    return r;
}
__device__ __forceinline__ void unpack2(unsigned long long v, float& lo, float& hi) {
    asm("mov.b64 {%0, %1}, %2;" : "=f"(lo), "=f"(hi) : "l"(v));
}
__device__ __forceinline__ void ffma2(unsigned long long& d,
                                      unsigned long long a,
                                      unsigned long long b) {
    asm("fma.rn.f32x2 %0, %1, %2, %0;" : "+l"(d) : "l"(a), "l"(b));
}

// ---------------------------------------------------------------------------
// zero scratch
// ---------------------------------------------------------------------------
__global__ void zero_kernel() {
    int i = blockIdx.x * blockDim.x + threadIdx.x;     // grid covers NCODE*DIM
    g_esum[i] = 0.0f;
    if (i < NCODE) g_counts[i] = 0.0f;
    if (i == 0)    g_loss = 0.0f;
}

// ---------------------------------------------------------------------------
// ||e_k||^2 per code (one warp per code)
// ---------------------------------------------------------------------------
__global__ void enorm_kernel(const float* __restrict__ emb) {
    int w = (blockIdx.x * blockDim.x + threadIdx.x) >> 5;
    int lane = threadIdx.x & 31;
    if (w >= NCODE) return;
    const float4* p = (const float4*)(emb + (size_t)w * DIM);
    float s = 0.0f;
#pragma unroll
    for (int c = 0; c < 2; c++) {
        float4 v = p[lane + 32 * c];
        s += v.x * v.x + v.y * v.y + v.z * v.z + v.w * v.w;
    }
#pragma unroll
    for (int o = 16; o >= 1; o >>= 1) s += __shfl_xor_sync(0xffffffffu, s, o);
    if (lane == 0) g_enorm[w] = s;
}

// ---------------------------------------------------------------------------
// Main fused kernel: distance GEMM + argmin + z_q gather + EMA scatter
// Block: 256 threads = 16(tx) x 16(ty). Tile: 128 rows x 128 codes.
// Per thread: 8 rows (ty + 16*i) x 8 cols (tx*8 .. tx*8+7, as 4 f32x2 pairs).
// ---------------------------------------------------------------------------
__global__ __launch_bounds__(256, 2)
void vq_main_kernel(const float* __restrict__ z, const float* __restrict__ emb,
                    float* __restrict__ out) {
    __shared__ __align__(16) float As[32][130];   // [k][row]
    __shared__ __align__(16) float Bs[32][130];   // [k][col]
    __shared__ int   sIdx[128];
    __shared__ float sRed[8];

    const int tid = threadIdx.x;
    const int tx  = tid & 15;
    const int ty  = tid >> 4;
    const int rowBase = blockIdx.x * 128;

    float best[8];
    int   bidx[8];
#pragma unroll
    for (int i = 0; i < 8; i++) { best[i] = 3.3e38f; bidx[i] = 0; }

    for (int n = 0; n < 8; n++) {               // 8 col-tiles of 128 codes
        unsigned long long acc[8][4];
#pragma unroll
        for (int i = 0; i < 8; i++)
#pragma unroll
            for (int j = 0; j < 4; j++) acc[i][j] = 0ull;

        for (int kc = 0; kc < 8; kc++) {        // 8 D-chunks of 32
            __syncthreads();                    // protect previous tile reads
            // load z tile [128 rows x 32 k] transposed into As[k][row]
#pragma unroll
            for (int rep = 0; rep < 4; rep++) {
                int idx4 = tid + rep * 256;     // 0..1023 float4 slots
                int r = idx4 >> 3;
                int c = idx4 & 7;
                float4 v = *(const float4*)(z + (size_t)(rowBase + r) * DIM + kc * 32 + c * 4);
                As[c * 4 + 0][r] = v.x; As[c * 4 + 1][r] = v.y;
                As[c * 4 + 2][r] = v.z; As[c * 4 + 3][r] = v.w;
            }
            // load embedding tile [128 codes x 32 k] into Bs[k][col]
#pragma unroll
            for (int rep = 0; rep < 4; rep++) {
                int idx4 = tid + rep * 256;
                int r = idx4 >> 3;
                int c = idx4 & 7;
                float4 v = *(const float4*)(emb + (size_t)(n * 128 + r) * DIM + kc * 32 + c * 4);
                Bs[c * 4 + 0][r] = v.x; Bs[c * 4 + 1][r] = v.y;
                Bs[c * 4 + 2][r] = v.z; Bs[c * 4 + 3][r] = v.w;
            }
            __syncthreads();
#pragma unroll
            for (int kk = 0; kk < 32; kk++) {
                unsigned long long a[8];
#pragma unroll
                for (int i = 0; i < 8; i++) {
                    float av = As[kk][ty + 16 * i];
                    a[i] = pack2(av, av);
                }
#pragma unroll
                for (int j = 0; j < 4; j++) {
                    unsigned long long b =
                        *(const unsigned long long*)&Bs[kk][tx * 8 + 2 * j];
#pragma unroll
                    for (int i = 0; i < 8; i++) ffma2(acc[i][j], a[i], b);
                }
            }
        }

        // distances (||x||^2 dropped: constant per row) and argmin
        float4 en0 = *(const float4*)&g_enorm[n * 128 + tx * 8];
        float4 en1 = *(const float4*)&g_enorm[n * 128 + tx * 8 + 4];
        float en[8] = {en0.x, en0.y, en0.z, en0.w, en1.x, en1.y, en1.z, en1.w};
#pragma unroll
        for (int i = 0; i < 8; i++) {
            float tb = 3.3e38f; int tc = 0;
#pragma unroll
            for (int j = 0; j < 4; j++) {
                float lo, hi; unpack2(acc[i][j], lo, hi);
                float d0 = en[2 * j]     - 2.0f * lo;
                float d1 = en[2 * j + 1] - 2.0f * hi;
                int c0 = n * 128 + tx * 8 + 2 * j;
                if (d0 < tb) { tb = d0; tc = c0; }
                if (d1 < tb) { tb = d1; tc = c0 + 1; }
            }
            // butterfly argmin across the 16 lanes sharing this row group
#pragma unroll
            for (int o = 8; o >= 1; o >>= 1) {
                float od = __shfl_xor_sync(0xffffffffu, tb, o, 16);
                int   oc = __shfl_xor_sync(0xffffffffu, tc, o, 16);
                if (od < tb || (od == tb && oc < tc)) { tb = od; tc = oc; }
            }
            if (tb < best[i] || (tb == best[i] && tc < bidx[i])) {
                best[i] = tb; bidx[i] = tc;
            }
        }
    }

    if (tx == 0) {
#pragma unroll
        for (int i = 0; i < 8; i++) sIdx[ty + 16 * i] = bidx[i];
    }
    __syncthreads();

    // output phase: z_q_st, indices, counts, embed_sum scatter, loss partial
    float lossAcc = 0.0f;
    const int d = tid;   // 256 threads == DIM
    for (int r = 0; r < 128; r++) {
        int code = sIdx[r];
        int row  = rowBase + r;
        float e  = emb[(size_t)code * DIM + d];
        float zv = z[(size_t)row * DIM + d];
        float diff = e - zv;                       // z_q - z
        out[OFF_ZQ + (size_t)row * DIM + d] = zv + diff;   // z + sg(z_q - z)
        lossAcc += diff * diff;
        atomicAdd(&g_esum[code * DIM + d], zv);
        if (tid == 0) {
            out[OFF_IDX + row] = (float)code;
            atomicAdd(&g_counts[code], 1.0f);
        }
    }
    // block-reduce loss
#pragma unroll
    for (int o = 16; o >= 1; o >>= 1) lossAcc += __shfl_xor_sync(0xffffffffu, lossAcc, o);
    if ((tid & 31) == 0) sRed[tid >> 5] = lossAcc;
    __syncthreads();
    if (tid < 8) {
        float v = sRed[tid];
#pragma unroll
        for (int o = 4; o >= 1; o >>= 1) v += __shfl_xor_sync(0xffu, v, o, 8);
        if (tid == 0) atomicAdd(&g_loss, v);
    }
}

// ---------------------------------------------------------------------------
// finalize 1: new_cluster_size, its sum, loss scalar
// ---------------------------------------------------------------------------
__global__ void fin1_kernel(const float* __restrict__ cs, float* __restrict__ out) {
    int k = threadIdx.x;   // 1024 threads
    float ncs = cs[k] * 0.99f + 0.01f * g_counts[k];
    out[OFF_CS + k] = ncs;

    __shared__ float red[32];
    float v = ncs;
#pragma unroll
    for (int o = 16; o >= 1; o >>= 1) v += __shfl_xor_sync(0xffffffffu, v, o);
    if ((k & 31) == 0) red[k >> 5] = v;
    __syncthreads();
    if (k < 32) {
        float t = red[k];
#pragma unroll
        for (int o = 16; o >= 1; o >>= 1) t += __shfl_xor_sync(0xffffffffu, t, o);
        if (k == 0) {
            g_nsum = t;
            out[OFF_LOSS] = 0.25f * g_loss / (float)(N_TOK * DIM);
        }
    }
}

// ---------------------------------------------------------------------------
// finalize 2: new_embedding_avg, new_embedding
// ---------------------------------------------------------------------------
__global__ void fin2_kernel(const float* __restrict__ avg, float* __restrict__ out) {
    int i = blockIdx.x * blockDim.x + threadIdx.x;   // covers NCODE*DIM
    float navg = avg[i] * 0.99f + 0.01f * g_esum[i];
    out[OFF_AVG + i] = navg;
    int k = i >> 8;
    float ncs = out[OFF_CS + k];
    float csn = (ncs + 1e-6f) / (g_nsum + (float)NCODE * 1e-6f);
    out[OFF_EMB + i] = navg / csn;
}

// ---------------------------------------------------------------------------
extern "C" void kernel_launch(void* const* d_in, const int* in_sizes, int n_in,
                              void* d_out, int out_size) {
    const float* z   = (const float*)d_in[0];   // [64,512,256]
    const float* emb = (const float*)d_in[1];   // [1024,256]
    const float* cs  = (const float*)d_in[2];   // [1024]
    const float* avg = (const float*)d_in[3];   // [1024,256]
    float* out = (float*)d_out;

    zero_kernel<<<(NCODE * DIM) / 256, 256>>>();
    enorm_kernel<<<(NCODE * 32) / 256, 256>>>(emb);
    vq_main_kernel<<<N_TOK / 128, 256>>>(z, emb, out);
    fin1_kernel<<<1, 1024>>>(cs, out);
    fin2_kernel<<<(NCODE * DIM) / 256, 256>>>(avg, out);
}

// round 3
// speedup vs baseline: 1.8947x; 1.8947x over previous
#include <cuda_runtime.h>
#include <cuda_fp16.h>
#include <cstdint>

#define N_TOK 32768
#define DIM   256
#define NCODE 1024

// d_out layout (float32): z_q_st, loss, indices, new_cluster_size,
// new_embedding_avg, new_embedding
#define OFF_ZQ   0
#define OFF_LOSS (N_TOK * DIM)
#define OFF_IDX  (OFF_LOSS + 1)
#define OFF_CS   (OFF_IDX + N_TOK)
#define OFF_AVG  (OFF_CS + NCODE)
#define OFF_EMB  (OFF_AVG + NCODE * DIM)

__device__ __align__(16) float g_enorm[NCODE];
__device__ float g_counts[NCODE];
__device__ float g_esum[NCODE * DIM];
__device__ float g_loss;
__device__ float g_nsum;
__device__ __align__(16) __half gAhi[N_TOK * DIM];   // 16 MB
__device__ __align__(16) __half gAlo[N_TOK * DIM];   // 16 MB
__device__ __align__(16) __half gBhi[NCODE * DIM];   // 512 KB
__device__ __align__(16) __half gBlo[NCODE * DIM];   // 512 KB

// ---------------------------------------------------------------------------
__device__ __forceinline__ uint32_t smem_u32(const void* p) {
    uint32_t a;
    asm("{ .reg .u64 t; cvta.to.shared.u64 t, %1; cvt.u32.u64 %0, t; }"
        : "=r"(a) : "l"(p));
    return a;
}
__device__ __forceinline__ void cp16(uint32_t dst, const void* src) {
    asm volatile("cp.async.cg.shared.global [%0], [%1], 16;"
                 :: "r"(dst), "l"(__cvta_generic_to_global(src)));
}
#define CP_COMMIT() asm volatile("cp.async.commit_group;" ::: "memory")
#define CP_WAIT1()  asm volatile("cp.async.wait_group 1;"  ::: "memory")

#define LDSM4(r0, r1, r2, r3, addr) asm volatile(                              \
    "ldmatrix.sync.aligned.m8n8.x4.shared.b16 {%0,%1,%2,%3}, [%4];"            \
    : "=r"(r0), "=r"(r1), "=r"(r2), "=r"(r3) : "r"(addr))

#define MMA(c, a0, a1, a2, a3, b0, b1) asm volatile(                           \
    "mma.sync.aligned.m16n8k16.row.col.f32.f16.f16.f32 "                       \
    "{%0,%1,%2,%3},{%4,%5,%6,%7},{%8,%9},{%0,%1,%2,%3};"                       \
    : "+f"((c)[0]), "+f"((c)[1]), "+f"((c)[2]), "+f"((c)[3])                   \
    : "r"(a0), "r"(a1), "r"(a2), "r"(a3), "r"(b0), "r"(b1))

__device__ __forceinline__ unsigned long long packDC(float d, int c) {
    unsigned u = __float_as_uint(d);
    u = (u & 0x80000000u) ? ~u : (u | 0x80000000u);
    return ((unsigned long long)u << 32) | (unsigned)c;
}

// ---------------------------------------------------------------------------
__global__ void zero_kernel() {
    int i = blockIdx.x * blockDim.x + threadIdx.x;
    g_esum[i] = 0.0f;
    if (i < NCODE) g_counts[i] = 0.0f;
    if (i == 0)    g_loss = 0.0f;
}

__global__ void enorm_kernel(const float* __restrict__ emb) {
    int w = (blockIdx.x * blockDim.x + threadIdx.x) >> 5;
    int lane = threadIdx.x & 31;
    if (w >= NCODE) return;
    const float4* p = (const float4*)(emb + (size_t)w * DIM);
    float s = 0.0f;
#pragma unroll
    for (int c = 0; c < 2; c++) {
        float4 v = p[lane + 32 * c];
        s += v.x * v.x + v.y * v.y + v.z * v.z + v.w * v.w;
    }
#pragma unroll
    for (int o = 16; o >= 1; o >>= 1) s += __shfl_xor_sync(0xffffffffu, s, o);
    if (lane == 0) g_enorm[w] = s;
}

// fp32 -> fp16 (hi, lo) split
__global__ void prep_kernel(const float* __restrict__ z, const float* __restrict__ emb) {
    int p = blockIdx.x * blockDim.x + threadIdx.x;   // one float2 per thread
    const int ZP = N_TOK * (DIM / 2);
    if (p < ZP) {
        float2 v = ((const float2*)z)[p];
        __half h0 = __float2half_rn(v.x), h1 = __float2half_rn(v.y);
        __half l0 = __float2half_rn(v.x - __half2float(h0));
        __half l1 = __float2half_rn(v.y - __half2float(h1));
        ((__half2*)gAhi)[p] = __halves2half2(h0, h1);
        ((__half2*)gAlo)[p] = __halves2half2(l0, l1);
    } else {
        int q = p - ZP;
        if (q >= NCODE * (DIM / 2)) return;
        float2 v = ((const float2*)emb)[q];
        __half h0 = __float2half_rn(v.x), h1 = __float2half_rn(v.y);
        __half l0 = __float2half_rn(v.x - __half2float(h0));
        __half l1 = __float2half_rn(v.y - __half2float(h1));
        ((__half2*)gBhi)[q] = __halves2half2(h0, h1);
        ((__half2*)gBlo)[q] = __halves2half2(l0, l1);
    }
}

// ---------------------------------------------------------------------------
// Main: HMMA fp16-split GEMM + argmin + outputs.
// CTA: 128 rows x 1024 codes (n-tiles of 256), 8 warps (2M x 4N), warp 64x64.
// smem rows padded to 80B (ldmatrix conflict-free: r*20 mod 32 distinct).
// ---------------------------------------------------------------------------
#define SM_A     0                       // 2 buf x (hi 10240 + lo 10240)
#define SM_B     40960                   // 2 buf x (hi 20480 + lo 20480)
#define SM_EN    122880                  // 4 KB
#define SM_BEST  126976                  // 128 x u64
#define SM_RED   128000                  // 8 floats
#define SM_TOTAL 128064

__global__ __launch_bounds__(256, 1)
void vq_main_kernel(const float* __restrict__ z, const float* __restrict__ emb,
                    float* __restrict__ out) {
    extern __shared__ char smem[];
    const uint32_t sb = smem_u32(smem);
    const int tid  = threadIdx.x;
    const int lane = tid & 31;
    const int wid  = tid >> 5;
    const int wm   = wid >> 2;           // 0..1  (M half)
    const int wn   = wid & 3;            // 0..3  (N quarter)
    const int rowBase = blockIdx.x * 128;

    float* sEnorm = (float*)(smem + SM_EN);
    unsigned long long* sBest = (unsigned long long*)(smem + SM_BEST);
    float* sRed = (float*)(smem + SM_RED);

#pragma unroll
    for (int i = 0; i < 4; i++) sEnorm[tid + i * 256] = g_enorm[tid + i * 256];
    if (tid < 128) sBest[tid] = ~0ull;

    // ldmatrix per-lane address offsets (bytes), row stride 80B
    const uint32_t aOff = (uint32_t)((wm * 64 + (lane & 15)) * 80 + (lane >> 4) * 16);
    const uint32_t bOff = (uint32_t)((wn * 64 + (lane & 7) + ((lane >> 4) << 3)) * 80
                                     + ((lane >> 3) & 1) * 16);

    float acc[4][8][4];
#pragma unroll
    for (int m = 0; m < 4; m++)
#pragma unroll
        for (int nf = 0; nf < 8; nf++)
#pragma unroll
            for (int v = 0; v < 4; v++) acc[m][nf][v] = 0.0f;

    float bestD[8];
    int   bestC[8];
#pragma unroll
    for (int i = 0; i < 8; i++) { bestD[i] = 3.4e38f; bestC[i] = 0; }

    // ---- prefetch helper (as macro over j) ----
#define PREFETCH(j) do {                                                       \
    int _n = (j) >> 3, _kc = (j) & 7, _buf = (j) & 1;                          \
    uint32_t _aD = sb + SM_A + _buf * 20480;                                   \
    uint32_t _bD = sb + SM_B + _buf * 40960;                                   \
    _Pragma("unroll")                                                          \
    for (int _it = 0; _it < 2; _it++) {                                        \
        int _cid = tid + _it * 256;                                            \
        int _row = _cid >> 2, _c4 = _cid & 3;                                  \
        size_t _so = (size_t)(rowBase + _row) * DIM + _kc * 32 + _c4 * 8;      \
        uint32_t _d = _aD + _row * 80 + _c4 * 16;                              \
        cp16(_d, gAhi + _so);                                                  \
        cp16(_d + 10240, gAlo + _so);                                          \
    }                                                                          \
    _Pragma("unroll")                                                          \
    for (int _it = 0; _it < 4; _it++) {                                        \
        int _cid = tid + _it * 256;                                            \
        int _row = _cid >> 2, _c4 = _cid & 3;                                  \
        size_t _so = (size_t)(_n * 256 + _row) * DIM + _kc * 32 + _c4 * 8;     \
        uint32_t _d = _bD + _row * 80 + _c4 * 16;                              \
        cp16(_d, gBhi + _so);                                                  \
        cp16(_d + 20480, gBlo + _so);                                          \
    }                                                                          \
} while (0)

    PREFETCH(0);
    CP_COMMIT();

    for (int it = 0; it < 32; it++) {
        if (it + 1 < 32) PREFETCH(it + 1);
        CP_COMMIT();
        CP_WAIT1();
        __syncthreads();

        const int buf = it & 1;
        const uint32_t aB = sb + SM_A + buf * 20480 + aOff;
        const uint32_t bB = sb + SM_B + buf * 40960 + bOff;

#pragma unroll
        for (int s = 0; s < 2; s++) {                    // two k16 steps
            uint32_t bh[8][2], bl[8][2];
#pragma unroll
            for (int q = 0; q < 4; q++) {                // n16 groups
                uint32_t r0, r1, r2, r3;
                LDSM4(r0, r1, r2, r3, bB + q * 1280 + s * 32);
                bh[2 * q][0] = r0; bh[2 * q][1] = r1;
                bh[2 * q + 1][0] = r2; bh[2 * q + 1][1] = r3;
                LDSM4(r0, r1, r2, r3, bB + q * 1280 + s * 32 + 20480);
                bl[2 * q][0] = r0; bl[2 * q][1] = r1;
                bl[2 * q + 1][0] = r2; bl[2 * q + 1][1] = r3;
            }
#pragma unroll
            for (int m = 0; m < 4; m++) {
                uint32_t ah0, ah1, ah2, ah3, al0, al1, al2, al3;
                LDSM4(ah0, ah1, ah2, ah3, aB + m * 1280 + s * 32);
                LDSM4(al0, al1, al2, al3, aB + m * 1280 + s * 32 + 10240);
#pragma unroll
                for (int nf = 0; nf < 8; nf++) {
                    MMA(acc[m][nf], ah0, ah1, ah2, ah3, bh[nf][0], bh[nf][1]);
                    MMA(acc[m][nf], ah0, ah1, ah2, ah3, bl[nf][0], bl[nf][1]);
                    MMA(acc[m][nf], al0, al1, al2, al3, bh[nf][0], bh[nf][1]);
                }
            }
        }

        if ((it & 7) == 7) {                             // end of n-tile
            const int n = it >> 3;
            const int colB = n * 256 + wn * 64 + 2 * (lane & 3);
#pragma unroll
            for (int nf = 0; nf < 8; nf++) {
                float2 en = *(const float2*)&sEnorm[colB + nf * 8];
                const int c0 = colB + nf * 8;
#pragma unroll
                for (int m = 0; m < 4; m++) {
                    float d0 = en.x - 2.0f * acc[m][nf][0];
                    float d1 = en.y - 2.0f * acc[m][nf][1];
                    float d2 = en.x - 2.0f * acc[m][nf][2];
                    float d3 = en.y - 2.0f * acc[m][nf][3];
                    if (d0 < bestD[2 * m]) { bestD[2 * m] = d0; bestC[2 * m] = c0; }
                    if (d1 < bestD[2 * m]) { bestD[2 * m] = d1; bestC[2 * m] = c0 + 1; }
                    if (d2 < bestD[2 * m + 1]) { bestD[2 * m + 1] = d2; bestC[2 * m + 1] = c0; }
                    if (d3 < bestD[2 * m + 1]) { bestD[2 * m + 1] = d3; bestC[2 * m + 1] = c0 + 1; }
                    acc[m][nf][0] = 0.0f; acc[m][nf][1] = 0.0f;
                    acc[m][nf][2] = 0.0f; acc[m][nf][3] = 0.0f;
                }
            }
        }
        __syncthreads();
    }

    // argmin reduce: quad shuffle (lanes sharing l>>2 own the same row)
#pragma unroll
    for (int sidx = 0; sidx < 8; sidx++) {
        float d = bestD[sidx]; int c = bestC[sidx];
#pragma unroll
        for (int off = 1; off <= 2; off <<= 1) {
            float od = __shfl_xor_sync(0xffffffffu, d, off);
            int   oc = __shfl_xor_sync(0xffffffffu, c, off);
            if (od < d || (od == d && oc < c)) { d = od; c = oc; }
        }
        if ((lane & 3) == 0) {
            int row = wm * 64 + (sidx >> 1) * 16 + (lane >> 2) + (sidx & 1) * 8;
            atomicMin(&sBest[row], packDC(d, c));
        }
    }
    __syncthreads();

    // output phase: z_q_st, indices, counts, embed_sum scatter, loss partial
    float lossAcc = 0.0f;
    const int d = tid;   // DIM == 256
    for (int r = 0; r < 128; r++) {
        int code = (int)(unsigned)(sBest[r] & 0xffffffffull);
        int row  = rowBase + r;
        float e  = emb[(size_t)code * DIM + d];
        float zv = z[(size_t)row * DIM + d];
        float diff = e - zv;
        out[OFF_ZQ + (size_t)row * DIM + d] = zv + diff;
        lossAcc += diff * diff;
        atomicAdd(&g_esum[code * DIM + d], zv);
        if (tid == 0) {
            out[OFF_IDX + row] = (float)code;
            atomicAdd(&g_counts[code], 1.0f);
        }
    }
#pragma unroll
    for (int o = 16; o >= 1; o >>= 1) lossAcc += __shfl_xor_sync(0xffffffffu, lossAcc, o);
    if (lane == 0) sRed[wid] = lossAcc;
    __syncthreads();
    if (tid < 8) {
        float v = sRed[tid];
#pragma unroll
        for (int o = 4; o >= 1; o >>= 1) v += __shfl_xor_sync(0xffu, v, o, 8);
        if (tid == 0) atomicAdd(&g_loss, v);
    }
}

// ---------------------------------------------------------------------------
__global__ void fin1_kernel(const float* __restrict__ cs, float* __restrict__ out) {
    int k = threadIdx.x;
    float ncs = cs[k] * 0.99f + 0.01f * g_counts[k];
    out[OFF_CS + k] = ncs;
    __shared__ float red[32];
    float v = ncs;
#pragma unroll
    for (int o = 16; o >= 1; o >>= 1) v += __shfl_xor_sync(0xffffffffu, v, o);
    if ((k & 31) == 0) red[k >> 5] = v;
    __syncthreads();
    if (k < 32) {
        float t = red[k];
#pragma unroll
        for (int o = 16; o >= 1; o >>= 1) t += __shfl_xor_sync(0xffffffffu, t, o);
        if (k == 0) {
            g_nsum = t;
            out[OFF_LOSS] = 0.25f * g_loss / (float)(N_TOK * DIM);
        }
    }
}

__global__ void fin2_kernel(const float* __restrict__ avg, float* __restrict__ out) {
    int i = blockIdx.x * blockDim.x + threadIdx.x;
    float navg = avg[i] * 0.99f + 0.01f * g_esum[i];
    out[OFF_AVG + i] = navg;
    int k = i >> 8;
    float ncs = out[OFF_CS + k];
    float csn = (ncs + 1e-6f) / (g_nsum + (float)NCODE * 1e-6f);
    out[OFF_EMB + i] = navg / csn;
}

// ---------------------------------------------------------------------------
extern "C" void kernel_launch(void* const* d_in, const int* in_sizes, int n_in,
                              void* d_out, int out_size) {
    const float* z   = (const float*)d_in[0];
    const float* emb = (const float*)d_in[1];
    const float* cs  = (const float*)d_in[2];
    const float* avg = (const float*)d_in[3];
    float* out = (float*)d_out;

    cudaFuncSetAttribute(vq_main_kernel,
                         cudaFuncAttributeMaxDynamicSharedMemorySize, SM_TOTAL);

    zero_kernel<<<(NCODE * DIM) / 256, 256>>>();
    enorm_kernel<<<(NCODE * 32) / 256, 256>>>(emb);
    prep_kernel<<<(N_TOK * 128 + NCODE * 128) / 256, 256>>>(z, emb);
    vq_main_kernel<<<N_TOK / 128, 256, SM_TOTAL>>>(z, emb, out);
    fin1_kernel<<<1, 1024>>>(cs, out);
    fin2_kernel<<<(NCODE * DIM) / 256, 256>>>(avg, out);
}

// round 4
// speedup vs baseline: 2.3904x; 1.2616x over previous
#include <cuda_runtime.h>
#include <cuda_fp16.h>
#include <cstdint>

#define N_TOK 32768
#define DIM   256
#define NCODE 1024

// d_out layout (float32): z_q_st, loss, indices, new_cluster_size,
// new_embedding_avg, new_embedding
#define OFF_ZQ   0
#define OFF_LOSS (N_TOK * DIM)
#define OFF_IDX  (OFF_LOSS + 1)
#define OFF_CS   (OFF_IDX + N_TOK)
#define OFF_AVG  (OFF_CS + NCODE)
#define OFF_EMB  (OFF_AVG + NCODE * DIM)

__device__ __align__(16) float g_enorm[NCODE];
__device__ float g_counts[NCODE];
__device__ float g_esum[NCODE * DIM];
__device__ float g_loss;
__device__ float g_nsum;
__device__ __align__(16) __half gAhi[N_TOK * DIM];   // 16 MB
__device__ __align__(16) __half gAlo[N_TOK * DIM];   // 16 MB
__device__ __align__(16) __half gBhi[NCODE * DIM];   // 512 KB
__device__ __align__(16) __half gBlo[NCODE * DIM];   // 512 KB

// ---------------------------------------------------------------------------
__device__ __forceinline__ uint32_t smem_u32(const void* p) {
    uint32_t a;
    asm("{ .reg .u64 t; cvta.to.shared.u64 t, %1; cvt.u32.u64 %0, t; }"
        : "=r"(a) : "l"(p));
    return a;
}
__device__ __forceinline__ void cp16(uint32_t dst, const void* src) {
    asm volatile("cp.async.cg.shared.global [%0], [%1], 16;"
                 :: "r"(dst), "l"(__cvta_generic_to_global(src)));
}
#define CP_COMMIT() asm volatile("cp.async.commit_group;" ::: "memory")
#define CP_WAIT1()  asm volatile("cp.async.wait_group 1;"  ::: "memory")

#define LDSM4(r0, r1, r2, r3, addr) asm volatile(                              \
    "ldmatrix.sync.aligned.m8n8.x4.shared.b16 {%0,%1,%2,%3}, [%4];"            \
    : "=r"(r0), "=r"(r1), "=r"(r2), "=r"(r3) : "r"(addr))

#define MMA(c, a0, a1, a2, a3, b0, b1) asm volatile(                           \
    "mma.sync.aligned.m16n8k16.row.col.f32.f16.f16.f32 "                       \
    "{%0,%1,%2,%3},{%4,%5,%6,%7},{%8,%9},{%0,%1,%2,%3};"                       \
    : "+f"((c)[0]), "+f"((c)[1]), "+f"((c)[2]), "+f"((c)[3])                   \
    : "r"(a0), "r"(a1), "r"(a2), "r"(a3), "r"(b0), "r"(b1))

__device__ __forceinline__ unsigned long long packDC(float d, int c) {
    unsigned u = __float_as_uint(d);
    u = (u & 0x80000000u) ? ~u : (u | 0x80000000u);
    return ((unsigned long long)u << 32) | (unsigned)c;
}

// ---------------------------------------------------------------------------
__global__ void zero_kernel() {
    int i = blockIdx.x * blockDim.x + threadIdx.x;
    g_esum[i] = 0.0f;
    if (i < NCODE) g_counts[i] = 0.0f;
    if (i == 0)    g_loss = 0.0f;
}

__global__ void enorm_kernel(const float* __restrict__ emb) {
    int w = (blockIdx.x * blockDim.x + threadIdx.x) >> 5;
    int lane = threadIdx.x & 31;
    if (w >= NCODE) return;
    const float4* p = (const float4*)(emb + (size_t)w * DIM);
    float s = 0.0f;
#pragma unroll
    for (int c = 0; c < 2; c++) {
        float4 v = p[lane + 32 * c];
        s += v.x * v.x + v.y * v.y + v.z * v.z + v.w * v.w;
    }
#pragma unroll
    for (int o = 16; o >= 1; o >>= 1) s += __shfl_xor_sync(0xffffffffu, s, o);
    if (lane == 0) g_enorm[w] = s;
}

// fp32 -> fp16 (hi, lo) split
__global__ void prep_kernel(const float* __restrict__ z, const float* __restrict__ emb) {
    int p = blockIdx.x * blockDim.x + threadIdx.x;   // one float2 per thread
    const int ZP = N_TOK * (DIM / 2);
    if (p < ZP) {
        float2 v = ((const float2*)z)[p];
        __half h0 = __float2half_rn(v.x), h1 = __float2half_rn(v.y);
        __half l0 = __float2half_rn(v.x - __half2float(h0));
        __half l1 = __float2half_rn(v.y - __half2float(h1));
        ((__half2*)gAhi)[p] = __halves2half2(h0, h1);
        ((__half2*)gAlo)[p] = __halves2half2(l0, l1);
    } else {
        int q = p - ZP;
        if (q >= NCODE * (DIM / 2)) return;
        float2 v = ((const float2*)emb)[q];
        __half h0 = __float2half_rn(v.x), h1 = __float2half_rn(v.y);
        __half l0 = __float2half_rn(v.x - __half2float(h0));
        __half l1 = __float2half_rn(v.y - __half2float(h1));
        ((__half2*)gBhi)[q] = __halves2half2(h0, h1);
        ((__half2*)gBlo)[q] = __halves2half2(l0, l1);
    }
}

// ---------------------------------------------------------------------------
// Main: HMMA fp16-split GEMM + argmin + outputs.
// CTA: 128 rows x 1024 codes (n-tiles of 128), 8 warps (2M x 4N), warp 64x32.
// acc = 64 regs/thread -> 2 CTAs/SM. smem rows padded to 80B (conflict-free).
// ---------------------------------------------------------------------------
#define SM_A     0                       // 2 buf x (hi 10240 + lo 10240)
#define SM_B     40960                   // 2 buf x (hi 10240 + lo 10240)
#define SM_EN    81920                   // 4 KB
#define SM_BEST  86016                   // 128 x u64
#define SM_RED   87040                   // 8 floats
#define SM_TOTAL 87104

__global__ __launch_bounds__(256, 2)
void vq_main_kernel(const float* __restrict__ z, const float* __restrict__ emb,
                    float* __restrict__ out) {
    extern __shared__ char smem[];
    const uint32_t sb = smem_u32(smem);
    const int tid  = threadIdx.x;
    const int lane = tid & 31;
    const int wid  = tid >> 5;
    const int wm   = wid >> 2;           // 0..1  (M half)
    const int wn   = wid & 3;            // 0..3  (N quarter, 32 cols each)
    const int rowBase = blockIdx.x * 128;

    float* sEnorm = (float*)(smem + SM_EN);
    unsigned long long* sBest = (unsigned long long*)(smem + SM_BEST);
    float* sRed = (float*)(smem + SM_RED);

#pragma unroll
    for (int i = 0; i < 4; i++) sEnorm[tid + i * 256] = g_enorm[tid + i * 256];
    if (tid < 128) sBest[tid] = ~0ull;

    // ldmatrix per-lane address offsets (bytes), row stride 80B
    const uint32_t aOff = (uint32_t)((wm * 64 + (lane & 15)) * 80 + (lane >> 4) * 16);
    const uint32_t bOff = (uint32_t)((wn * 32 + (lane & 7) + ((lane >> 4) << 3)) * 80
                                     + ((lane >> 3) & 1) * 16);

    float acc[4][4][4];
#pragma unroll
    for (int m = 0; m < 4; m++)
#pragma unroll
        for (int nf = 0; nf < 4; nf++)
#pragma unroll
            for (int v = 0; v < 4; v++) acc[m][nf][v] = 0.0f;

    float bestD[8];
    int   bestC[8];
#pragma unroll
    for (int i = 0; i < 8; i++) { bestD[i] = 3.4e38f; bestC[i] = 0; }

    // ---- prefetch: j = n*8 + kc, 64 iterations total ----
#define PREFETCH(j) do {                                                       \
    int _n = (j) >> 3, _kc = (j) & 7, _buf = (j) & 1;                          \
    uint32_t _aD = sb + SM_A + _buf * 20480;                                   \
    uint32_t _bD = sb + SM_B + _buf * 20480;                                   \
    _Pragma("unroll")                                                          \
    for (int _it = 0; _it < 2; _it++) {                                        \
        int _cid = tid + _it * 256;                                            \
        int _row = _cid >> 2, _c4 = _cid & 3;                                  \
        size_t _so = (size_t)(rowBase + _row) * DIM + _kc * 32 + _c4 * 8;      \
        uint32_t _d = _aD + _row * 80 + _c4 * 16;                              \
        cp16(_d, gAhi + _so);                                                  \
        cp16(_d + 10240, gAlo + _so);                                          \
    }                                                                          \
    _Pragma("unroll")                                                          \
    for (int _it = 0; _it < 2; _it++) {                                        \
        int _cid = tid + _it * 256;                                            \
        int _row = _cid >> 2, _c4 = _cid & 3;                                  \
        size_t _so = (size_t)(_n * 128 + _row) * DIM + _kc * 32 + _c4 * 8;     \
        uint32_t _d = _bD + _row * 80 + _c4 * 16;                              \
        cp16(_d, gBhi + _so);                                                  \
        cp16(_d + 10240, gBlo + _so);                                          \
    }                                                                          \
} while (0)

    PREFETCH(0);
    CP_COMMIT();

    for (int it = 0; it < 64; it++) {
        if (it + 1 < 64) PREFETCH(it + 1);
        CP_COMMIT();
        CP_WAIT1();
        __syncthreads();

        const int buf = it & 1;
        const uint32_t aB = sb + SM_A + buf * 20480 + aOff;
        const uint32_t bB = sb + SM_B + buf * 20480 + bOff;

#pragma unroll
        for (int s = 0; s < 2; s++) {                    // two k16 steps
            uint32_t bh[4][2], bl[4][2];
#pragma unroll
            for (int q = 0; q < 2; q++) {                // n16 groups (32 cols)
                uint32_t r0, r1, r2, r3;
                LDSM4(r0, r1, r2, r3, bB + q * 1280 + s * 32);
                bh[2 * q][0] = r0; bh[2 * q][1] = r1;
                bh[2 * q + 1][0] = r2; bh[2 * q + 1][1] = r3;
                LDSM4(r0, r1, r2, r3, bB + q * 1280 + s * 32 + 10240);
                bl[2 * q][0] = r0; bl[2 * q][1] = r1;
                bl[2 * q + 1][0] = r2; bl[2 * q + 1][1] = r3;
            }
#pragma unroll
            for (int m = 0; m < 4; m++) {
                uint32_t ah0, ah1, ah2, ah3, al0, al1, al2, al3;
                LDSM4(ah0, ah1, ah2, ah3, aB + m * 1280 + s * 32);
                LDSM4(al0, al1, al2, al3, aB + m * 1280 + s * 32 + 10240);
#pragma unroll
                for (int nf = 0; nf < 4; nf++) {
                    MMA(acc[m][nf], ah0, ah1, ah2, ah3, bh[nf][0], bh[nf][1]);
                    MMA(acc[m][nf], ah0, ah1, ah2, ah3, bl[nf][0], bl[nf][1]);
                    MMA(acc[m][nf], al0, al1, al2, al3, bh[nf][0], bh[nf][1]);
                }
            }
        }

        if ((it & 7) == 7) {                             // end of n-tile
            const int n = it >> 3;
            const int colB = n * 128 + wn * 32 + 2 * (lane & 3);
#pragma unroll
            for (int nf = 0; nf < 4; nf++) {
                float2 en = *(const float2*)&sEnorm[colB + nf * 8];
                const int c0 = colB + nf * 8;
#pragma unroll
                for (int m = 0; m < 4; m++) {
                    float d0 = en.x - 2.0f * acc[m][nf][0];
                    float d1 = en.y - 2.0f * acc[m][nf][1];
                    float d2 = en.x - 2.0f * acc[m][nf][2];
                    float d3 = en.y - 2.0f * acc[m][nf][3];
                    if (d0 < bestD[2 * m]) { bestD[2 * m] = d0; bestC[2 * m] = c0; }
                    if (d1 < bestD[2 * m]) { bestD[2 * m] = d1; bestC[2 * m] = c0 + 1; }
                    if (d2 < bestD[2 * m + 1]) { bestD[2 * m + 1] = d2; bestC[2 * m + 1] = c0; }
                    if (d3 < bestD[2 * m + 1]) { bestD[2 * m + 1] = d3; bestC[2 * m + 1] = c0 + 1; }
                    acc[m][nf][0] = 0.0f; acc[m][nf][1] = 0.0f;
                    acc[m][nf][2] = 0.0f; acc[m][nf][3] = 0.0f;
                }
            }
        }
        __syncthreads();
    }

    // argmin reduce: quad shuffle (lanes sharing l>>2 own the same row)
#pragma unroll
    for (int sidx = 0; sidx < 8; sidx++) {
        float d = bestD[sidx]; int c = bestC[sidx];
#pragma unroll
        for (int off = 1; off <= 2; off <<= 1) {
            float od = __shfl_xor_sync(0xffffffffu, d, off);
            int   oc = __shfl_xor_sync(0xffffffffu, c, off);
            if (od < d || (od == d && oc < c)) { d = od; c = oc; }
        }
        if ((lane & 3) == 0) {
            int row = wm * 64 + (sidx >> 1) * 16 + (lane >> 2) + (sidx & 1) * 8;
            atomicMin(&sBest[row], packDC(d, c));
        }
    }
    __syncthreads();

    // indices + counts (parallel, once)
    if (tid < 128) {
        int code = (int)(unsigned)(sBest[tid] & 0xffffffffull);
        out[OFF_IDX + rowBase + tid] = (float)code;
        atomicAdd(&g_counts[code], 1.0f);
    }

    // output phase: z_q_st, embed_sum scatter, loss partial
    float lossAcc = 0.0f;
    const int d = tid;   // DIM == 256
    for (int r = 0; r < 128; r++) {
        int code = (int)(unsigned)(sBest[r] & 0xffffffffull);
        int row  = rowBase + r;
        float e  = emb[(size_t)code * DIM + d];
        float zv = z[(size_t)row * DIM + d];
        float diff = e - zv;
        out[OFF_ZQ + (size_t)row * DIM + d] = zv + diff;
        lossAcc += diff * diff;
        atomicAdd(&g_esum[code * DIM + d], zv);
    }
#pragma unroll
    for (int o = 16; o >= 1; o >>= 1) lossAcc += __shfl_xor_sync(0xffffffffu, lossAcc, o);
    if (lane == 0) sRed[wid] = lossAcc;
    __syncthreads();
    if (tid < 8) {
        float v = sRed[tid];
#pragma unroll
        for (int o = 4; o >= 1; o >>= 1) v += __shfl_xor_sync(0xffu, v, o, 8);
        if (tid == 0) atomicAdd(&g_loss, v);
    }
}

// ---------------------------------------------------------------------------
__global__ void fin1_kernel(const float* __restrict__ cs, float* __restrict__ out) {
    int k = threadIdx.x;
    float ncs = cs[k] * 0.99f + 0.01f * g_counts[k];
    out[OFF_CS + k] = ncs;
    __shared__ float red[32];
    float v = ncs;
#pragma unroll
    for (int o = 16; o >= 1; o >>= 1) v += __shfl_xor_sync(0xffffffffu, v, o);
    if ((k & 31) == 0) red[k >> 5] = v;
    __syncthreads();
    if (k < 32) {
        float t = red[k];
#pragma unroll
        for (int o = 16; o >= 1; o >>= 1) t += __shfl_xor_sync(0xffffffffu, t, o);
        if (k == 0) {
            g_nsum = t;
            out[OFF_LOSS] = 0.25f * g_loss / (float)(N_TOK * DIM);
        }
    }
}

__global__ void fin2_kernel(const float* __restrict__ avg, float* __restrict__ out) {
    int i = blockIdx.x * blockDim.x + threadIdx.x;
    float navg = avg[i] * 0.99f + 0.01f * g_esum[i];
    out[OFF_AVG + i] = navg;
    int k = i >> 8;
    float ncs = out[OFF_CS + k];
    float csn = (ncs + 1e-6f) / (g_nsum + (float)NCODE * 1e-6f);
    out[OFF_EMB + i] = navg / csn;
}

// ---------------------------------------------------------------------------
extern "C" void kernel_launch(void* const* d_in, const int* in_sizes, int n_in,
                              void* d_out, int out_size) {
    const float* z   = (const float*)d_in[0];
    const float* emb = (const float*)d_in[1];
    const float* cs  = (const float*)d_in[2];
    const float* avg = (const float*)d_in[3];
    float* out = (float*)d_out;

    cudaFuncSetAttribute(vq_main_kernel,
                         cudaFuncAttributeMaxDynamicSharedMemorySize, SM_TOTAL);

    zero_kernel<<<(NCODE * DIM) / 256, 256>>>();
    enorm_kernel<<<(NCODE * 32) / 256, 256>>>(emb);
    prep_kernel<<<(N_TOK * 128 + NCODE * 128) / 256, 256>>>(z, emb);
    vq_main_kernel<<<N_TOK / 128, 256, SM_TOTAL>>>(z, emb, out);
    fin1_kernel<<<1, 1024>>>(cs, out);
    fin2_kernel<<<(NCODE * DIM) / 256, 256>>>(avg, out);
}

// round 6
// speedup vs baseline: 4.0680x; 1.7018x over previous
#include <cuda_runtime.h>
#include <cuda_bf16.h>
#include <cstdint>

#define N_TOK 32768
#define DIM   256
#define NCODE 1024
#define TAU   3.0f
#define CAP   48

// d_out layout (float32): z_q_st, loss, indices, new_cluster_size,
// new_embedding_avg, new_embedding
#define OFF_ZQ   0
#define OFF_LOSS (N_TOK * DIM)
#define OFF_IDX  (OFF_LOSS + 1)
#define OFF_CS   (OFF_IDX + N_TOK)
#define OFF_AVG  (OFF_CS + NCODE)
#define OFF_EMB  (OFF_AVG + NCODE * DIM)

__device__ __align__(16) float g_enorm[NCODE];
__device__ float g_counts[NCODE];
__device__ float g_esum[NCODE * DIM];
__device__ float g_loss;
__device__ float g_nsum;
__device__ __align__(16) __nv_bfloat16 gA[N_TOK * DIM];   // 16 MB
__device__ __align__(16) __nv_bfloat16 gB[NCODE * DIM];   // 512 KB

// ---------------------------------------------------------------------------
__device__ __forceinline__ uint32_t smem_u32(const void* p) {
    uint32_t a;
    asm("{ .reg .u64 t; cvta.to.shared.u64 t, %1; cvt.u32.u64 %0, t; }"
        : "=r"(a) : "l"(p));
    return a;
}
__device__ __forceinline__ void cp16(uint32_t dst, const void* src) {
    asm volatile("cp.async.cg.shared.global [%0], [%1], 16;"
                 :: "r"(dst), "l"(__cvta_generic_to_global(src)));
}
#define CP_COMMIT() asm volatile("cp.async.commit_group;" ::: "memory")
#define CP_WAIT2()  asm volatile("cp.async.wait_group 2;"  ::: "memory")

#define LDSM4(r0, r1, r2, r3, addr) asm volatile(                              \
    "ldmatrix.sync.aligned.m8n8.x4.shared.b16 {%0,%1,%2,%3}, [%4];"            \
    : "=r"(r0), "=r"(r1), "=r"(r2), "=r"(r3) : "r"(addr))

#define MMA(c, a0, a1, a2, a3, b0, b1) asm volatile(                           \
    "mma.sync.aligned.m16n8k16.row.col.f32.bf16.bf16.f32 "                     \
    "{%0,%1,%2,%3},{%4,%5,%6,%7},{%8,%9},{%0,%1,%2,%3};"                       \
    : "+f"((c)[0]), "+f"((c)[1]), "+f"((c)[2]), "+f"((c)[3])                   \
    : "r"(a0), "r"(a1), "r"(a2), "r"(a3), "r"(b0), "r"(b1))

__device__ __forceinline__ unsigned mapf(float d) {
    unsigned u = __float_as_uint(d);
    return (u & 0x80000000u) ? ~u : (u | 0x80000000u);
}
__device__ __forceinline__ float unmapf(unsigned x) {
    return (x & 0x80000000u) ? __uint_as_float(x & 0x7fffffffu)
                             : __uint_as_float(~x);
}

// ---------------------------------------------------------------------------
__global__ void zero_kernel() {
    int i = blockIdx.x * blockDim.x + threadIdx.x;
    g_esum[i] = 0.0f;
    if (i < NCODE) g_counts[i] = 0.0f;
    if (i == 0)    g_loss = 0.0f;
}

__global__ void enorm_kernel(const float* __restrict__ emb) {
    int w = (blockIdx.x * blockDim.x + threadIdx.x) >> 5;
    int lane = threadIdx.x & 31;
    if (w >= NCODE) return;
    const float4* p = (const float4*)(emb + (size_t)w * DIM);
    float s = 0.0f;
#pragma unroll
    for (int c = 0; c < 2; c++) {
        float4 v = p[lane + 32 * c];
        s += v.x * v.x + v.y * v.y + v.z * v.z + v.w * v.w;
    }
#pragma unroll
    for (int o = 16; o >= 1; o >>= 1) s += __shfl_xor_sync(0xffffffffu, s, o);
    if (lane == 0) g_enorm[w] = s;
}

// fp32 -> bf16 round
__global__ void prep_kernel(const float* __restrict__ z, const float* __restrict__ emb) {
    int p = blockIdx.x * blockDim.x + threadIdx.x;   // one float2 per thread
    const int ZP = N_TOK * (DIM / 2);
    if (p < ZP) {
        float2 v = ((const float2*)z)[p];
        ((__nv_bfloat162*)gA)[p] =
            __halves2bfloat162(__float2bfloat16_rn(v.x), __float2bfloat16_rn(v.y));
    } else {
        int q = p - ZP;
        if (q >= NCODE * (DIM / 2)) return;
        float2 v = ((const float2*)emb)[q];
        ((__nv_bfloat162*)gB)[q] =
            __halves2bfloat162(__float2bfloat16_rn(v.x), __float2bfloat16_rn(v.y));
    }
}

// ---------------------------------------------------------------------------
// Main: single-pass bf16 HMMA approx GEMM + windowed candidate collection +
// exact fp32 refinement + outputs.
// CTA: 128 rows x 1024 codes (n-tiles of 128), 8 warps (2M x 4N), warp 64x32.
// 4-stage cp.async pipeline, one __syncthreads per k-iter.
// smem rows padded to 80B (16B-aligned for cp.async; ldmatrix conflict-free).
// ---------------------------------------------------------------------------
#define STAGE_SZ 20480                   // A 128x80 + B 128x80
#define SM_EN    81920                   // 4 KB
#define SM_CAND  86016                   // 128 x CAP x 4 = 24576
#define SM_MINU  110592                  // 128 x u32
#define SM_CNT   111104                  // 128 x int
#define SM_BESTC 111616                  // 128 x int
#define SM_RED   112128                  // 8 floats
#define SM_TOTAL 112192

__global__ __launch_bounds__(256, 2)
void vq_main_kernel(const float* __restrict__ z, const float* __restrict__ emb,
                    float* __restrict__ out) {
    extern __shared__ char smem[];
    const uint32_t sb = smem_u32(smem);
    const int tid  = threadIdx.x;
    const int lane = tid & 31;
    const int wid  = tid >> 5;
    const int wm   = wid >> 2;           // 0..1  (M half)
    const int wn   = wid & 3;            // 0..3  (N quarter, 32 cols)
    const int rowBase = blockIdx.x * 128;

    float*    sEnorm = (float*)(smem + SM_EN);
    int*      sCand  = (int*)(smem + SM_CAND);
    unsigned* sMinU  = (unsigned*)(smem + SM_MINU);
    int*      sCnt   = (int*)(smem + SM_CNT);
    int*      sBestC = (int*)(smem + SM_BESTC);
    float*    sRed   = (float*)(smem + SM_RED);

#pragma unroll
    for (int i = 0; i < 4; i++) sEnorm[tid + i * 256] = g_enorm[tid + i * 256];
    if (tid < 128) { sMinU[tid] = 0xffffffffu; sCnt[tid] = 0; }

    // ldmatrix per-lane address offsets (bytes), row stride 80B
    const uint32_t aOff = (uint32_t)((wm * 64 + (lane & 15)) * 80 + (lane >> 4) * 16);
    const uint32_t bOff = (uint32_t)((wn * 32 + (lane & 7) + ((lane >> 4) << 3)) * 80
                                     + ((lane >> 3) & 1) * 16);

    float acc[4][4][4];
#pragma unroll
    for (int m = 0; m < 4; m++)
#pragma unroll
        for (int nf = 0; nf < 4; nf++)
#pragma unroll
            for (int v = 0; v < 4; v++) acc[m][nf][v] = 0.0f;

    // ---- prefetch: j = n*8 + kc ----
#define PREFETCH(j) do {                                                       \
    int _n = (j) >> 3, _kc = (j) & 7;                                          \
    uint32_t _base = sb + ((j) & 3) * STAGE_SZ;                                \
    _Pragma("unroll")                                                          \
    for (int _it = 0; _it < 2; _it++) {                                        \
        int _cid = tid + _it * 256;                                            \
        int _row = _cid >> 2, _c4 = _cid & 3;                                  \
        cp16(_base + _row * 80 + _c4 * 16,                                     \
             gA + (size_t)(rowBase + _row) * DIM + _kc * 32 + _c4 * 8);        \
    }                                                                          \
    _Pragma("unroll")                                                          \
    for (int _it = 0; _it < 2; _it++) {                                        \
        int _cid = tid + _it * 256;                                            \
        int _row = _cid >> 2, _c4 = _cid & 3;                                  \
        cp16(_base + 10240 + _row * 80 + _c4 * 16,                             \
             gB + (size_t)(_n * 128 + _row) * DIM + _kc * 32 + _c4 * 8);       \
    }                                                                          \
} while (0)

    PREFETCH(0); CP_COMMIT();
    PREFETCH(1); CP_COMMIT();
    PREFETCH(2); CP_COMMIT();

    for (int it = 0; it < 64; it++) {
        CP_WAIT2();
        __syncthreads();

        const uint32_t stBase = sb + (it & 3) * STAGE_SZ;
        const uint32_t aB = stBase + aOff;
        const uint32_t bB = stBase + 10240 + bOff;

#pragma unroll
        for (int s = 0; s < 2; s++) {                    // two k16 steps
            uint32_t b[4][2];
#pragma unroll
            for (int q = 0; q < 2; q++) {
                uint32_t r0, r1, r2, r3;
                LDSM4(r0, r1, r2, r3, bB + q * 1280 + s * 32);
                b[2 * q][0] = r0; b[2 * q][1] = r1;
                b[2 * q + 1][0] = r2; b[2 * q + 1][1] = r3;
            }
#pragma unroll
            for (int m = 0; m < 4; m++) {
                uint32_t a0, a1, a2, a3;
                LDSM4(a0, a1, a2, a3, aB + m * 1280 + s * 32);
#pragma unroll
                for (int nf = 0; nf < 4; nf++)
                    MMA(acc[m][nf], a0, a1, a2, a3, b[nf][0], b[nf][1]);
            }
        }

        if ((it & 7) == 7) {                             // end of n-tile
            const int n = it >> 3;
            const int colB = n * 128 + wn * 32 + 2 * (lane & 3);
            // pass 1: settle per-row approx min
#pragma unroll
            for (int m = 0; m < 4; m++) {
                int r0 = wm * 64 + m * 16 + (lane >> 2);
                float bd0 = 3.4e38f, bd1 = 3.4e38f;
#pragma unroll
                for (int nf = 0; nf < 4; nf++) {
                    float2 en = *(const float2*)&sEnorm[colB + nf * 8];
                    bd0 = fminf(bd0, fminf(en.x - 2.0f * acc[m][nf][0],
                                           en.y - 2.0f * acc[m][nf][1]));
                    bd1 = fminf(bd1, fminf(en.x - 2.0f * acc[m][nf][2],
                                           en.y - 2.0f * acc[m][nf][3]));
                }
#pragma unroll
                for (int off = 1; off <= 2; off <<= 1) {
                    bd0 = fminf(bd0, __shfl_xor_sync(0xffffffffu, bd0, off));
                    bd1 = fminf(bd1, __shfl_xor_sync(0xffffffffu, bd1, off));
                }
                if ((lane & 3) == 0) {
                    atomicMin(&sMinU[r0], mapf(bd0));
                    atomicMin(&sMinU[r0 + 8], mapf(bd1));
                }
            }
            __syncthreads();
            // pass 2: collect candidates within TAU of settled min
#pragma unroll
            for (int m = 0; m < 4; m++) {
                int r0 = wm * 64 + m * 16 + (lane >> 2);
                float thr0 = unmapf(sMinU[r0]) + TAU;
                float thr1 = unmapf(sMinU[r0 + 8]) + TAU;
#pragma unroll
                for (int nf = 0; nf < 4; nf++) {
                    float2 en = *(const float2*)&sEnorm[colB + nf * 8];
                    float d0 = en.x - 2.0f * acc[m][nf][0];
                    float d1 = en.y - 2.0f * acc[m][nf][1];
                    float d2 = en.x - 2.0f * acc[m][nf][2];
                    float d3 = en.y - 2.0f * acc[m][nf][3];
                    int c0 = colB + nf * 8;
                    if (d0 < thr0) { int p = atomicAdd(&sCnt[r0], 1);     if (p < CAP) sCand[r0 * CAP + p] = c0; }
                    if (d1 < thr0) { int p = atomicAdd(&sCnt[r0], 1);     if (p < CAP) sCand[r0 * CAP + p] = c0 + 1; }
                    if (d2 < thr1) { int p = atomicAdd(&sCnt[r0 + 8], 1); if (p < CAP) sCand[(r0 + 8) * CAP + p] = c0; }
                    if (d3 < thr1) { int p = atomicAdd(&sCnt[r0 + 8], 1); if (p < CAP) sCand[(r0 + 8) * CAP + p] = c0 + 1; }
                    acc[m][nf][0] = 0.0f; acc[m][nf][1] = 0.0f;
                    acc[m][nf][2] = 0.0f; acc[m][nf][3] = 0.0f;
                }
            }
        }

        if (it + 3 < 64) PREFETCH(it + 3);
        CP_COMMIT();
    }
    __syncthreads();

    // ---- exact fp32 refinement: warp w handles rows [w*16, w*16+16) ----
    for (int rr = 0; rr < 16; rr++) {
        int r = wid * 16 + rr;
        int cnt = sCnt[r]; if (cnt > CAP) cnt = CAP;
        const float* zr = z + (size_t)(rowBase + r) * DIM;
        float zv[8];
#pragma unroll
        for (int j = 0; j < 8; j++) zv[j] = zr[lane + 32 * j];
        float bestd = 3.4e38f; int bestc = 0;
        for (int i = 0; i < cnt; i++) {
            int c = sCand[r * CAP + i];
            const float* er = emb + (size_t)c * DIM;
            float dot = 0.0f;
#pragma unroll
            for (int j = 0; j < 8; j++) dot += zv[j] * er[lane + 32 * j];
#pragma unroll
            for (int o = 16; o >= 1; o >>= 1) dot += __shfl_xor_sync(0xffffffffu, dot, o);
            float dd = sEnorm[c] - 2.0f * dot;
            if (dd < bestd || (dd == bestd && c < bestc)) { bestd = dd; bestc = c; }
        }
        if (lane == 0) sBestC[r] = bestc;
    }
    __syncthreads();

    // indices + counts
    if (tid < 128) {
        int code = sBestC[tid];
        out[OFF_IDX + rowBase + tid] = (float)code;
        atomicAdd(&g_counts[code], 1.0f);
    }

    // output phase: z_q_st, embed_sum scatter, loss partial
    float lossAcc = 0.0f;
    const int d = tid;   // DIM == 256
    for (int r = 0; r < 128; r++) {
        int code = sBestC[r];
        int row  = rowBase + r;
        float e  = emb[(size_t)code * DIM + d];
        float zv = z[(size_t)row * DIM + d];
        float diff = e - zv;
        out[OFF_ZQ + (size_t)row * DIM + d] = zv + diff;
        lossAcc += diff * diff;
        atomicAdd(&g_esum[code * DIM + d], zv);
    }
#pragma unroll
    for (int o = 16; o >= 1; o >>= 1) lossAcc += __shfl_xor_sync(0xffffffffu, lossAcc, o);
    if (lane == 0) sRed[wid] = lossAcc;
    __syncthreads();
    if (tid < 8) {
        float v = sRed[tid];
#pragma unroll
        for (int o = 4; o >= 1; o >>= 1) v += __shfl_xor_sync(0xffu, v, o, 8);
        if (tid == 0) atomicAdd(&g_loss, v);
    }
}

// ---------------------------------------------------------------------------
__global__ void fin1_kernel(const float* __restrict__ cs, float* __restrict__ out) {
    int k = threadIdx.x;
    float ncs = cs[k] * 0.99f + 0.01f * g_counts[k];
    out[OFF_CS + k] = ncs;
    __shared__ float red[32];
    float v = ncs;
#pragma unroll
    for (int o = 16; o >= 1; o >>= 1) v += __shfl_xor_sync(0xffffffffu, v, o);
    if ((k & 31) == 0) red[k >> 5] = v;
    __syncthreads();
    if (k < 32) {
        float t = red[k];
#pragma unroll
        for (int o = 16; o >= 1; o >>= 1) t += __shfl_xor_sync(0xffffffffu, t, o);
        if (k == 0) {
            g_nsum = t;
            out[OFF_LOSS] = 0.25f * g_loss / (float)(N_TOK * DIM);
        }
    }
}

__global__ void fin2_kernel(const float* __restrict__ avg, float* __restrict__ out) {
    int i = blockIdx.x * blockDim.x + threadIdx.x;
    float navg = avg[i] * 0.99f + 0.01f * g_esum[i];
    out[OFF_AVG + i] = navg;
    int k = i >> 8;
    float ncs = out[OFF_CS + k];
    float csn = (ncs + 1e-6f) / (g_nsum + (float)NCODE * 1e-6f);
    out[OFF_EMB + i] = navg / csn;
}

// ---------------------------------------------------------------------------
extern "C" void kernel_launch(void* const* d_in, const int* in_sizes, int n_in,
                              void* d_out, int out_size) {
    const float* z   = (const float*)d_in[0];
    const float* emb = (const float*)d_in[1];
    const float* cs  = (const float*)d_in[2];
    const float* avg = (const float*)d_in[3];
    float* out = (float*)d_out;

    cudaFuncSetAttribute(vq_main_kernel,
                         cudaFuncAttributeMaxDynamicSharedMemorySize, SM_TOTAL);

    zero_kernel<<<(NCODE * DIM) / 256, 256>>>();
    enorm_kernel<<<(NCODE * 32) / 256, 256>>>(emb);
    prep_kernel<<<(N_TOK * 128 + NCODE * 128) / 256, 256>>>(z, emb);
    vq_main_kernel<<<N_TOK / 128, 256, SM_TOTAL>>>(z, emb, out);
    fin1_kernel<<<1, 1024>>>(cs, out);
    fin2_kernel<<<(NCODE * DIM) / 256, 256>>>(avg, out);
}

// round 7
// speedup vs baseline: 4.3482x; 1.0689x over previous
#include <cuda_runtime.h>
#include <cuda_bf16.h>
#include <cstdint>

#define N_TOK 32768
#define DIM   256
#define NCODE 1024
#define TAU   3.0f
#define CAP   48

// d_out layout (float32): z_q_st, loss, indices, new_cluster_size,
// new_embedding_avg, new_embedding
#define OFF_ZQ   0
#define OFF_LOSS (N_TOK * DIM)
#define OFF_IDX  (OFF_LOSS + 1)
#define OFF_CS   (OFF_IDX + N_TOK)
#define OFF_AVG  (OFF_CS + NCODE)
#define OFF_EMB  (OFF_AVG + NCODE * DIM)

__device__ __align__(16) float g_enorm[NCODE];
__device__ float g_counts[NCODE];
__device__ float g_esum[NCODE * DIM];
__device__ float g_loss;
__device__ float g_nsum;
__device__ __align__(16) __nv_bfloat16 gA[N_TOK * DIM];   // 16 MB
__device__ __align__(16) __nv_bfloat16 gB[NCODE * DIM];   // 512 KB
__device__ int g_cnt[N_TOK];
__device__ int g_cand[N_TOK * CAP];                       // 6.3 MB

// ---------------------------------------------------------------------------
__device__ __forceinline__ uint32_t smem_u32(const void* p) {
    uint32_t a;
    asm("{ .reg .u64 t; cvta.to.shared.u64 t, %1; cvt.u32.u64 %0, t; }"
        : "=r"(a) : "l"(p));
    return a;
}
__device__ __forceinline__ void cp16(uint32_t dst, const void* src) {
    asm volatile("cp.async.cg.shared.global [%0], [%1], 16;"
                 :: "r"(dst), "l"(__cvta_generic_to_global(src)));
}
#define CP_COMMIT() asm volatile("cp.async.commit_group;" ::: "memory")
#define CP_WAIT2()  asm volatile("cp.async.wait_group 2;"  ::: "memory")

#define LDSM4(r0, r1, r2, r3, addr) asm volatile(                              \
    "ldmatrix.sync.aligned.m8n8.x4.shared.b16 {%0,%1,%2,%3}, [%4];"            \
    : "=r"(r0), "=r"(r1), "=r"(r2), "=r"(r3) : "r"(addr))

#define MMA(c, a0, a1, a2, a3, b0, b1) asm volatile(                           \
    "mma.sync.aligned.m16n8k16.row.col.f32.bf16.bf16.f32 "                     \
    "{%0,%1,%2,%3},{%4,%5,%6,%7},{%8,%9},{%0,%1,%2,%3};"                       \
    : "+f"((c)[0]), "+f"((c)[1]), "+f"((c)[2]), "+f"((c)[3])                   \
    : "r"(a0), "r"(a1), "r"(a2), "r"(a3), "r"(b0), "r"(b1))

__device__ __forceinline__ unsigned mapf(float d) {
    unsigned u = __float_as_uint(d);
    return (u & 0x80000000u) ? ~u : (u | 0x80000000u);
}
__device__ __forceinline__ float unmapf(unsigned x) {
    return (x & 0x80000000u) ? __uint_as_float(x & 0x7fffffffu)
                             : __uint_as_float(~x);
}

// ---------------------------------------------------------------------------
__global__ void zero_kernel() {
    int i = blockIdx.x * blockDim.x + threadIdx.x;
    g_esum[i] = 0.0f;
    if (i < NCODE) g_counts[i] = 0.0f;
    if (i == 0)    g_loss = 0.0f;
}

__global__ void enorm_kernel(const float* __restrict__ emb) {
    int w = (blockIdx.x * blockDim.x + threadIdx.x) >> 5;
    int lane = threadIdx.x & 31;
    if (w >= NCODE) return;
    const float4* p = (const float4*)(emb + (size_t)w * DIM);
    float s = 0.0f;
#pragma unroll
    for (int c = 0; c < 2; c++) {
        float4 v = p[lane + 32 * c];
        s += v.x * v.x + v.y * v.y + v.z * v.z + v.w * v.w;
    }
#pragma unroll
    for (int o = 16; o >= 1; o >>= 1) s += __shfl_xor_sync(0xffffffffu, s, o);
    if (lane == 0) g_enorm[w] = s;
}

// fp32 -> bf16 round
__global__ void prep_kernel(const float* __restrict__ z, const float* __restrict__ emb) {
    int p = blockIdx.x * blockDim.x + threadIdx.x;   // one float2 per thread
    const int ZP = N_TOK * (DIM / 2);
    if (p < ZP) {
        float2 v = ((const float2*)z)[p];
        ((__nv_bfloat162*)gA)[p] =
            __halves2bfloat162(__float2bfloat16_rn(v.x), __float2bfloat16_rn(v.y));
    } else {
        int q = p - ZP;
        if (q >= NCODE * (DIM / 2)) return;
        float2 v = ((const float2*)emb)[q];
        ((__nv_bfloat162*)gB)[q] =
            __halves2bfloat162(__float2bfloat16_rn(v.x), __float2bfloat16_rn(v.y));
    }
}

// ---------------------------------------------------------------------------
// Main: single-pass bf16 HMMA approx GEMM + windowed candidate collection.
// CTA: 128 rows x 1024 codes (n-tiles of 128), 8 warps (2M x 4N), warp 64x32.
// 4-stage cp.async pipeline. smem rows padded to 80B.
// ---------------------------------------------------------------------------
#define STAGE_SZ 20480                   // A 128x80 + B 128x80
#define SM_EN    81920                   // 4 KB
#define SM_CAND  86016                   // 128 x CAP x 4 = 24576
#define SM_MINU  110592                  // 128 x u32
#define SM_CNT   111104                  // 128 x int
#define SM_TOTAL 111616

__global__ __launch_bounds__(256, 2)
void vq_main_kernel(float* __restrict__ out) {
    extern __shared__ char smem[];
    const uint32_t sb = smem_u32(smem);
    const int tid  = threadIdx.x;
    const int lane = tid & 31;
    const int wid  = tid >> 5;
    const int wm   = wid >> 2;           // 0..1  (M half)
    const int wn   = wid & 3;            // 0..3  (N quarter, 32 cols)
    const int rowBase = blockIdx.x * 128;

    float*    sEnorm = (float*)(smem + SM_EN);
    int*      sCand  = (int*)(smem + SM_CAND);
    unsigned* sMinU  = (unsigned*)(smem + SM_MINU);
    int*      sCnt   = (int*)(smem + SM_CNT);

#pragma unroll
    for (int i = 0; i < 4; i++) sEnorm[tid + i * 256] = g_enorm[tid + i * 256];
    if (tid < 128) { sMinU[tid] = 0xffffffffu; sCnt[tid] = 0; }

    // ldmatrix per-lane address offsets (bytes), row stride 80B
    const uint32_t aOff = (uint32_t)((wm * 64 + (lane & 15)) * 80 + (lane >> 4) * 16);
    const uint32_t bOff = (uint32_t)((wn * 32 + (lane & 7) + ((lane >> 4) << 3)) * 80
                                     + ((lane >> 3) & 1) * 16);

    float acc[4][4][4];
#pragma unroll
    for (int m = 0; m < 4; m++)
#pragma unroll
        for (int nf = 0; nf < 4; nf++)
#pragma unroll
            for (int v = 0; v < 4; v++) acc[m][nf][v] = 0.0f;

    // ---- prefetch: j = n*8 + kc ----
#define PREFETCH(j) do {                                                       \
    int _n = (j) >> 3, _kc = (j) & 7;                                          \
    uint32_t _base = sb + ((j) & 3) * STAGE_SZ;                                \
    _Pragma("unroll")                                                          \
    for (int _it = 0; _it < 2; _it++) {                                        \
        int _cid = tid + _it * 256;                                            \
        int _row = _cid >> 2, _c4 = _cid & 3;                                  \
        cp16(_base + _row * 80 + _c4 * 16,                                     \
             gA + (size_t)(rowBase + _row) * DIM + _kc * 32 + _c4 * 8);        \
    }                                                                          \
    _Pragma("unroll")                                                          \
    for (int _it = 0; _it < 2; _it++) {                                        \
        int _cid = tid + _it * 256;                                            \
        int _row = _cid >> 2, _c4 = _cid & 3;                                  \
        cp16(_base + 10240 + _row * 80 + _c4 * 16,                             \
             gB + (size_t)(_n * 128 + _row) * DIM + _kc * 32 + _c4 * 8);       \
    }                                                                          \
} while (0)

    PREFETCH(0); CP_COMMIT();
    PREFETCH(1); CP_COMMIT();
    PREFETCH(2); CP_COMMIT();

    for (int it = 0; it < 64; it++) {
        CP_WAIT2();
        __syncthreads();

        const uint32_t stBase = sb + (it & 3) * STAGE_SZ;
        const uint32_t aB = stBase + aOff;
        const uint32_t bB = stBase + 10240 + bOff;

#pragma unroll
        for (int s = 0; s < 2; s++) {                    // two k16 steps
            uint32_t b[4][2];
#pragma unroll
            for (int q = 0; q < 2; q++) {
                uint32_t r0, r1, r2, r3;
                LDSM4(r0, r1, r2, r3, bB + q * 1280 + s * 32);
                b[2 * q][0] = r0; b[2 * q][1] = r1;
                b[2 * q + 1][0] = r2; b[2 * q + 1][1] = r3;
            }
#pragma unroll
            for (int m = 0; m < 4; m++) {
                uint32_t a0, a1, a2, a3;
                LDSM4(a0, a1, a2, a3, aB + m * 1280 + s * 32);
#pragma unroll
                for (int nf = 0; nf < 4; nf++)
                    MMA(acc[m][nf], a0, a1, a2, a3, b[nf][0], b[nf][1]);
            }
        }

        if ((it & 7) == 7) {                             // end of n-tile
            const int n = it >> 3;
            const int colB = n * 128 + wn * 32 + 2 * (lane & 3);
            // pass 1: settle per-row approx min
#pragma unroll
            for (int m = 0; m < 4; m++) {
                int r0 = wm * 64 + m * 16 + (lane >> 2);
                float bd0 = 3.4e38f, bd1 = 3.4e38f;
#pragma unroll
                for (int nf = 0; nf < 4; nf++) {
                    float2 en = *(const float2*)&sEnorm[colB + nf * 8];
                    bd0 = fminf(bd0, fminf(en.x - 2.0f * acc[m][nf][0],
                                           en.y - 2.0f * acc[m][nf][1]));
                    bd1 = fminf(bd1, fminf(en.x - 2.0f * acc[m][nf][2],
                                           en.y - 2.0f * acc[m][nf][3]));
                }
#pragma unroll
                for (int off = 1; off <= 2; off <<= 1) {
                    bd0 = fminf(bd0, __shfl_xor_sync(0xffffffffu, bd0, off));
                    bd1 = fminf(bd1, __shfl_xor_sync(0xffffffffu, bd1, off));
                }
                if ((lane & 3) == 0) {
                    atomicMin(&sMinU[r0], mapf(bd0));
                    atomicMin(&sMinU[r0 + 8], mapf(bd1));
                }
            }
            __syncthreads();
            // pass 2: collect candidates within TAU of settled min
#pragma unroll
            for (int m = 0; m < 4; m++) {
                int r0 = wm * 64 + m * 16 + (lane >> 2);
                float thr0 = unmapf(sMinU[r0]) + TAU;
                float thr1 = unmapf(sMinU[r0 + 8]) + TAU;
#pragma unroll
                for (int nf = 0; nf < 4; nf++) {
                    float2 en = *(const float2*)&sEnorm[colB + nf * 8];
                    float d0 = en.x - 2.0f * acc[m][nf][0];
                    float d1 = en.y - 2.0f * acc[m][nf][1];
                    float d2 = en.x - 2.0f * acc[m][nf][2];
                    float d3 = en.y - 2.0f * acc[m][nf][3];
                    int c0 = colB + nf * 8;
                    if (d0 < thr0) { int p = atomicAdd(&sCnt[r0], 1);     if (p < CAP) sCand[r0 * CAP + p] = c0; }
                    if (d1 < thr0) { int p = atomicAdd(&sCnt[r0], 1);     if (p < CAP) sCand[r0 * CAP + p] = c0 + 1; }
                    if (d2 < thr1) { int p = atomicAdd(&sCnt[r0 + 8], 1); if (p < CAP) sCand[(r0 + 8) * CAP + p] = c0; }
                    if (d3 < thr1) { int p = atomicAdd(&sCnt[r0 + 8], 1); if (p < CAP) sCand[(r0 + 8) * CAP + p] = c0 + 1; }
                    acc[m][nf][0] = 0.0f; acc[m][nf][1] = 0.0f;
                    acc[m][nf][2] = 0.0f; acc[m][nf][3] = 0.0f;
                }
            }
        }

        if (it + 3 < 64) PREFETCH(it + 3);
        CP_COMMIT();
    }
    __syncthreads();

    // dump candidate lists to global (warp w -> rows w*16..w*16+15)
    for (int rr = 0; rr < 16; rr++) {
        int r = wid * 16 + rr;
        int cnt = sCnt[r]; if (cnt > CAP) cnt = CAP;
        if (lane == 0) g_cnt[rowBase + r] = cnt;
        for (int i = lane; i < cnt; i += 32)
            g_cand[(size_t)(rowBase + r) * CAP + i] = sCand[r * CAP + i];
    }
}

// ---------------------------------------------------------------------------
// Refine + output kernel: grid N_TOK/16, 256 threads.
// Phase A: warp w refines rows (base + w*2, +1) exactly in fp32.
// Phase B: all threads write z_q_st / loss / esum / counts for 16 rows.
// ---------------------------------------------------------------------------
__global__ __launch_bounds__(256, 8)
void outref_kernel(const float* __restrict__ z, const float* __restrict__ emb,
                   float* __restrict__ out) {
    __shared__ int   sBestC[16];
    __shared__ float sRed[8];
    const int tid  = threadIdx.x;
    const int lane = tid & 31;
    const int wid  = tid >> 5;
    const int rowBase = blockIdx.x * 16;

#pragma unroll
    for (int rr = 0; rr < 2; rr++) {
        int r = rowBase + wid * 2 + rr;
        int cnt = g_cnt[r]; if (cnt > CAP) cnt = CAP;
        const float* zr = z + (size_t)r * DIM;
        float zv[8];
#pragma unroll
        for (int j = 0; j < 8; j++) zv[j] = zr[lane + 32 * j];
        float bestd = 3.4e38f; int bestc = 0;
        for (int i = 0; i < cnt; i++) {
            int c = g_cand[(size_t)r * CAP + i];
            const float* er = emb + (size_t)c * DIM;
            float dot = 0.0f;
#pragma unroll
            for (int j = 0; j < 8; j++) dot += zv[j] * er[lane + 32 * j];
#pragma unroll
            for (int o = 16; o >= 1; o >>= 1) dot += __shfl_xor_sync(0xffffffffu, dot, o);
            float dd = g_enorm[c] - 2.0f * dot;
            if (dd < bestd || (dd == bestd && c < bestc)) { bestd = dd; bestc = c; }
        }
        if (lane == 0) {
            sBestC[wid * 2 + rr] = bestc;
            out[OFF_IDX + r] = (float)bestc;
            atomicAdd(&g_counts[bestc], 1.0f);
        }
    }
    __syncthreads();

    float lossAcc = 0.0f;
    const int d = tid;   // DIM == 256
#pragma unroll
    for (int rr = 0; rr < 16; rr++) {
        int code = sBestC[rr];
        int row  = rowBase + rr;
        float e  = emb[(size_t)code * DIM + d];
        float zvv = z[(size_t)row * DIM + d];
        float diff = e - zvv;
        out[OFF_ZQ + (size_t)row * DIM + d] = zvv + diff;
        lossAcc += diff * diff;
        atomicAdd(&g_esum[code * DIM + d], zvv);
    }
#pragma unroll
    for (int o = 16; o >= 1; o >>= 1) lossAcc += __shfl_xor_sync(0xffffffffu, lossAcc, o);
    if (lane == 0) sRed[wid] = lossAcc;
    __syncthreads();
    if (tid < 8) {
        float v = sRed[tid];
#pragma unroll
        for (int o = 4; o >= 1; o >>= 1) v += __shfl_xor_sync(0xffu, v, o, 8);
        if (tid == 0) atomicAdd(&g_loss, v);
    }
}

// ---------------------------------------------------------------------------
__global__ void fin1_kernel(const float* __restrict__ cs, float* __restrict__ out) {
    int k = threadIdx.x;
    float ncs = cs[k] * 0.99f + 0.01f * g_counts[k];
    out[OFF_CS + k] = ncs;
    __shared__ float red[32];
    float v = ncs;
#pragma unroll
    for (int o = 16; o >= 1; o >>= 1) v += __shfl_xor_sync(0xffffffffu, v, o);
    if ((k & 31) == 0) red[k >> 5] = v;
    __syncthreads();
    if (k < 32) {
        float t = red[k];
#pragma unroll
        for (int o = 16; o >= 1; o >>= 1) t += __shfl_xor_sync(0xffffffffu, t, o);
        if (k == 0) {
            g_nsum = t;
            out[OFF_LOSS] = 0.25f * g_loss / (float)(N_TOK * DIM);
        }
    }
}

__global__ void fin2_kernel(const float* __restrict__ avg, float* __restrict__ out) {
    int i = blockIdx.x * blockDim.x + threadIdx.x;
    float navg = avg[i] * 0.99f + 0.01f * g_esum[i];
    out[OFF_AVG + i] = navg;
    int k = i >> 8;
    float ncs = out[OFF_CS + k];
    float csn = (ncs + 1e-6f) / (g_nsum + (float)NCODE * 1e-6f);
    out[OFF_EMB + i] = navg / csn;
}

// ---------------------------------------------------------------------------
extern "C" void kernel_launch(void* const* d_in, const int* in_sizes, int n_in,
                              void* d_out, int out_size) {
    const float* z   = (const float*)d_in[0];
    const float* emb = (const float*)d_in[1];
    const float* cs  = (const float*)d_in[2];
    const float* avg = (const float*)d_in[3];
    float* out = (float*)d_out;

    cudaFuncSetAttribute(vq_main_kernel,
                         cudaFuncAttributeMaxDynamicSharedMemorySize, SM_TOTAL);

    zero_kernel<<<(NCODE * DIM) / 256, 256>>>();
    enorm_kernel<<<(NCODE * 32) / 256, 256>>>(emb);
    prep_kernel<<<(N_TOK * 128 + NCODE * 128) / 256, 256>>>(z, emb);
    vq_main_kernel<<<N_TOK / 128, 256, SM_TOTAL>>>(out);
    outref_kernel<<<N_TOK / 16, 256>>>(z, emb, out);
    fin1_kernel<<<1, 1024>>>(cs, out);
    fin2_kernel<<<(NCODE * DIM) / 256, 256>>>(avg, out);
}

// round 8
// speedup vs baseline: 4.8819x; 1.1227x over previous
#include <cuda_runtime.h>
#include <cuda_bf16.h>
#include <cstdint>

#define N_TOK 32768
#define DIM   256
#define NCODE 1024
#define TAU   3.0f
#define CAP   48

// d_out layout (float32): z_q_st, loss, indices, new_cluster_size,
// new_embedding_avg, new_embedding
#define OFF_ZQ   0
#define OFF_LOSS (N_TOK * DIM)
#define OFF_IDX  (OFF_LOSS + 1)
#define OFF_CS   (OFF_IDX + N_TOK)
#define OFF_AVG  (OFF_CS + NCODE)
#define OFF_EMB  (OFF_AVG + NCODE * DIM)

#define TILE_B   10240                   // 128 rows x 80 B (64 B data + pad)

__device__ __align__(16) float g_enorm[NCODE];
__device__ float g_counts[NCODE];
__device__ float g_esum[NCODE * DIM];
__device__ float g_loss;
__device__ float g_nsum;
// tile-contiguous bf16 images: gAt[block][kc][row*80 + c*2], gBt[n][kc][...]
__device__ __align__(16) uint8_t gAt[(N_TOK / 128) * 8 * TILE_B];   // 21 MB
__device__ __align__(16) uint8_t gBt[(NCODE / 128) * 8 * TILE_B];   // 655 KB
__device__ int g_cnt[N_TOK];
__device__ int g_cand[N_TOK * CAP];

// ---------------------------------------------------------------------------
__device__ __forceinline__ uint32_t smem_u32(const void* p) {
    uint32_t a;
    asm("{ .reg .u64 t; cvta.to.shared.u64 t, %1; cvt.u32.u64 %0, t; }"
        : "=r"(a) : "l"(p));
    return a;
}
#define MBAR_INIT(a, c) asm volatile("mbarrier.init.shared.b64 [%0], %1;" \
    :: "r"(a), "r"(c) : "memory")
#define MBAR_EXPECT_TX(a, b) asm volatile(                                    \
    "mbarrier.arrive.expect_tx.shared.b64 _, [%0], %1;"                       \
    :: "r"(a), "r"(b) : "memory")
#define MBAR_WAIT(a, ph) do {                                               \
    uint32_t _m = (a), _p = (ph), _d;                                       \
    asm volatile("{\n\t.reg .pred p;\n\t"                                   \
        "mbarrier.try_wait.parity.acquire.cta.shared::cta.b64 p, [%1], %2;\n\t" \
        "selp.b32 %0, 1, 0, p;\n\t}" : "=r"(_d) : "r"(_m), "r"(_p) : "memory"); \
    if (!_d) {                                                              \
        asm volatile("{\n\t.reg .pred P1;\n\tWL%=:\n\t"                     \
            "mbarrier.try_wait.parity.acquire.cta.shared::cta.b64 P1, [%0], %1, 0x989680;\n\t" \
            "@P1 bra.uni WD%=;\n\tbra.uni WL%=;\n\tWD%=:\n\t}"              \
            :: "r"(_m), "r"(_p) : "memory");                                \
    } } while (0)
#define FENCE_ASYNC() asm volatile("fence.proxy.async.shared::cta;" ::: "memory")

__device__ __forceinline__ void bulk_g2s(uint32_t dst, const void* src,
                                         uint32_t bytes, uint32_t mbar) {
    asm volatile(
        "cp.async.bulk.shared::cta.global.mbarrier::complete_tx::bytes "
        "[%0], [%1], %2, [%3];"
        :: "r"(dst), "l"(__cvta_generic_to_global(src)), "r"(bytes), "r"(mbar)
        : "memory");
}

#define LDSM4(r0, r1, r2, r3, addr) asm volatile(                              \
    "ldmatrix.sync.aligned.m8n8.x4.shared.b16 {%0,%1,%2,%3}, [%4];"            \
    : "=r"(r0), "=r"(r1), "=r"(r2), "=r"(r3) : "r"(addr))

#define MMA(c, a0, a1, a2, a3, b0, b1) asm volatile(                           \
    "mma.sync.aligned.m16n8k16.row.col.f32.bf16.bf16.f32 "                     \
    "{%0,%1,%2,%3},{%4,%5,%6,%7},{%8,%9},{%0,%1,%2,%3};"                       \
    : "+f"((c)[0]), "+f"((c)[1]), "+f"((c)[2]), "+f"((c)[3])                   \
    : "r"(a0), "r"(a1), "r"(a2), "r"(a3), "r"(b0), "r"(b1))

__device__ __forceinline__ unsigned mapf(float d) {
    unsigned u = __float_as_uint(d);
    return (u & 0x80000000u) ? ~u : (u | 0x80000000u);
}
__device__ __forceinline__ float unmapf(unsigned x) {
    return (x & 0x80000000u) ? __uint_as_float(x & 0x7fffffffu)
                             : __uint_as_float(~x);
}

// ---------------------------------------------------------------------------
__global__ void enorm_kernel(const float* __restrict__ emb) {
    int w = (blockIdx.x * blockDim.x + threadIdx.x) >> 5;
    int lane = threadIdx.x & 31;
    if (w >= NCODE) return;
    const float4* p = (const float4*)(emb + (size_t)w * DIM);
    float s = 0.0f;
#pragma unroll
    for (int c = 0; c < 2; c++) {
        float4 v = p[lane + 32 * c];
        s += v.x * v.x + v.y * v.y + v.z * v.z + v.w * v.w;
    }
#pragma unroll
    for (int o = 16; o >= 1; o >>= 1) s += __shfl_xor_sync(0xffffffffu, s, o);
    if (lane == 0) g_enorm[w] = s;
}

// prep: fp32 -> bf16 into tile-contiguous layout; also zeroes scratch.
// Ranges: [0, AC)          A chunks (16B each)
//         [AC, AC+BC)      B chunks
//         [AC+BC, +ZC)     zero g_esum/counts/loss (float4 granules)
#define AC (N_TOK * DIM / 8)             // 1,048,576
#define BC (NCODE * DIM / 8)             // 32,768
#define ZC (NCODE * DIM / 4)             // 65,536
__global__ void prep_kernel(const float* __restrict__ z, const float* __restrict__ emb) {
    int p = blockIdx.x * blockDim.x + threadIdx.x;
    if (p < AC) {
        int t = p >> 9, w = p & 511;             // tile, chunk-within
        int row = w >> 2, c4 = w & 3;
        int b = t >> 3, kc = t & 7;
        const float* src = z + (size_t)(b * 128 + row) * DIM + kc * 32 + c4 * 8;
        float4 v0 = *(const float4*)src;
        float4 v1 = *(const float4*)(src + 4);
        __nv_bfloat162 o0 = __halves2bfloat162(__float2bfloat16_rn(v0.x), __float2bfloat16_rn(v0.y));
        __nv_bfloat162 o1 = __halves2bfloat162(__float2bfloat16_rn(v0.z), __float2bfloat16_rn(v0.w));
        __nv_bfloat162 o2 = __halves2bfloat162(__float2bfloat16_rn(v1.x), __float2bfloat16_rn(v1.y));
        __nv_bfloat162 o3 = __halves2bfloat162(__float2bfloat16_rn(v1.z), __float2bfloat16_rn(v1.w));
        uint4 pack = {*(uint32_t*)&o0, *(uint32_t*)&o1, *(uint32_t*)&o2, *(uint32_t*)&o3};
        *(uint4*)(gAt + (size_t)t * TILE_B + row * 80 + c4 * 16) = pack;
    } else if (p < AC + BC) {
        int q = p - AC;
        int t = q >> 9, w = q & 511;
        int row = w >> 2, c4 = w & 3;
        int n = t >> 3, kc = t & 7;
        const float* src = emb + (size_t)(n * 128 + row) * DIM + kc * 32 + c4 * 8;
        float4 v0 = *(const float4*)src;
        float4 v1 = *(const float4*)(src + 4);
        __nv_bfloat162 o0 = __halves2bfloat162(__float2bfloat16_rn(v0.x), __float2bfloat16_rn(v0.y));
        __nv_bfloat162 o1 = __halves2bfloat162(__float2bfloat16_rn(v0.z), __float2bfloat16_rn(v0.w));
        __nv_bfloat162 o2 = __halves2bfloat162(__float2bfloat16_rn(v1.x), __float2bfloat16_rn(v1.y));
        __nv_bfloat162 o3 = __halves2bfloat162(__float2bfloat16_rn(v1.z), __float2bfloat16_rn(v1.w));
        uint4 pack = {*(uint32_t*)&o0, *(uint32_t*)&o1, *(uint32_t*)&o2, *(uint32_t*)&o3};
        *(uint4*)(gBt + (size_t)t * TILE_B + row * 80 + c4 * 16) = pack;
    } else {
        int zi = p - AC - BC;
        if (zi >= ZC) return;
        ((float4*)g_esum)[zi] = make_float4(0.f, 0.f, 0.f, 0.f);
        if (zi < NCODE / 4) ((float4*)g_counts)[zi] = make_float4(0.f, 0.f, 0.f, 0.f);
        if (zi == 0) g_loss = 0.0f;
    }
}

// ---------------------------------------------------------------------------
// Main: bulk-copy-fed bf16 HMMA approx GEMM + windowed candidate collection.
// CTA: 128 rows x 1024 codes (n-tiles of 128), 8 warps (2M x 4N), warp 64x32.
// 4-stage cp.async.bulk + mbarrier pipeline. smem rows 80B stride.
// ---------------------------------------------------------------------------
#define STAGE_SZ 20480                   // A 10240 + B 10240
#define SM_EN    81920                   // 4 KB
#define SM_CAND  86016                   // 128 x CAP x 4 = 24576
#define SM_MINU  110592                  // 128 x u32
#define SM_CNT   111104                  // 128 x int
#define SM_MBAR  111616                  // 4 x 8 B
#define SM_TOTAL 111680

__global__ __launch_bounds__(256, 2)
void vq_main_kernel() {
    extern __shared__ char smem[];
    const uint32_t sb = smem_u32(smem);
    const int tid  = threadIdx.x;
    const int lane = tid & 31;
    const int wid  = tid >> 5;
    const int wm   = wid >> 2;           // 0..1  (M half)
    const int wn   = wid & 3;            // 0..3  (N quarter, 32 cols)
    const int rowBase = blockIdx.x * 128;

    float*    sEnorm = (float*)(smem + SM_EN);
    int*      sCand  = (int*)(smem + SM_CAND);
    unsigned* sMinU  = (unsigned*)(smem + SM_MINU);
    int*      sCnt   = (int*)(smem + SM_CNT);

#pragma unroll
    for (int i = 0; i < 4; i++) sEnorm[tid + i * 256] = g_enorm[tid + i * 256];
    if (tid < 128) { sMinU[tid] = 0xffffffffu; sCnt[tid] = 0; }
    if (tid == 0) {
#pragma unroll
        for (int s = 0; s < 4; s++) MBAR_INIT(sb + SM_MBAR + s * 8, 1);
    }
    __syncthreads();
    FENCE_ASYNC();

    // producer: j = n*8 + kc
#define ISSUE(j) do {                                                          \
    int _s = (j) & 3;                                                          \
    uint32_t _st = sb + _s * STAGE_SZ;                                         \
    uint32_t _mb = sb + SM_MBAR + _s * 8;                                      \
    MBAR_EXPECT_TX(_mb, STAGE_SZ);                                             \
    bulk_g2s(_st, gAt + (size_t)(blockIdx.x * 8 + ((j) & 7)) * TILE_B,         \
             TILE_B, _mb);                                                     \
    bulk_g2s(_st + TILE_B, gBt + (size_t)(j) * TILE_B, TILE_B, _mb);           \
} while (0)
    // note: gBt tile index for j = n*8+kc is exactly j (n-major, kc-minor)

    if (tid == 0) { ISSUE(0); ISSUE(1); ISSUE(2); }

    // ldmatrix per-lane address offsets (bytes), row stride 80B
    const uint32_t aOff = (uint32_t)((wm * 64 + (lane & 15)) * 80 + (lane >> 4) * 16);
    const uint32_t bOff = (uint32_t)((wn * 32 + (lane & 7) + ((lane >> 4) << 3)) * 80
                                     + ((lane >> 3) & 1) * 16);

    float acc[4][4][4];
#pragma unroll
    for (int m = 0; m < 4; m++)
#pragma unroll
        for (int nf = 0; nf < 4; nf++)
#pragma unroll
            for (int v = 0; v < 4; v++) acc[m][nf][v] = 0.0f;

    for (int it = 0; it < 64; it++) {
        MBAR_WAIT(sb + SM_MBAR + (it & 3) * 8, (it >> 2) & 1);

        const uint32_t stBase = sb + (it & 3) * STAGE_SZ;
        const uint32_t aB = stBase + aOff;
        const uint32_t bB = stBase + TILE_B + bOff;

#pragma unroll
        for (int s = 0; s < 2; s++) {                    // two k16 steps
            uint32_t b[4][2];
#pragma unroll
            for (int q = 0; q < 2; q++) {
                uint32_t r0, r1, r2, r3;
                LDSM4(r0, r1, r2, r3, bB + q * 1280 + s * 32);
                b[2 * q][0] = r0; b[2 * q][1] = r1;
                b[2 * q + 1][0] = r2; b[2 * q + 1][1] = r3;
            }
#pragma unroll
            for (int m = 0; m < 4; m++) {
                uint32_t a0, a1, a2, a3;
                LDSM4(a0, a1, a2, a3, aB + m * 1280 + s * 32);
#pragma unroll
                for (int nf = 0; nf < 4; nf++)
                    MMA(acc[m][nf], a0, a1, a2, a3, b[nf][0], b[nf][1]);
            }
        }

        if ((it & 7) == 7) {                             // end of n-tile
            const int n = it >> 3;
            const int colB = n * 128 + wn * 32 + 2 * (lane & 3);
            // pass 1: settle per-row approx min
#pragma unroll
            for (int m = 0; m < 4; m++) {
                int r0 = wm * 64 + m * 16 + (lane >> 2);
                float bd0 = 3.4e38f, bd1 = 3.4e38f;
#pragma unroll
                for (int nf = 0; nf < 4; nf++) {
                    float2 en = *(const float2*)&sEnorm[colB + nf * 8];
                    bd0 = fminf(bd0, fminf(en.x - 2.0f * acc[m][nf][0],
                                           en.y - 2.0f * acc[m][nf][1]));
                    bd1 = fminf(bd1, fminf(en.x - 2.0f * acc[m][nf][2],
                                           en.y - 2.0f * acc[m][nf][3]));
                }
#pragma unroll
                for (int off = 1; off <= 2; off <<= 1) {
                    bd0 = fminf(bd0, __shfl_xor_sync(0xffffffffu, bd0, off));
                    bd1 = fminf(bd1, __shfl_xor_sync(0xffffffffu, bd1, off));
                }
                if ((lane & 3) == 0) {
                    atomicMin(&sMinU[r0], mapf(bd0));
                    atomicMin(&sMinU[r0 + 8], mapf(bd1));
                }
            }
            __syncthreads();
            // pass 2: collect candidates within TAU of settled min
#pragma unroll
            for (int m = 0; m < 4; m++) {
                int r0 = wm * 64 + m * 16 + (lane >> 2);
                float thr0 = unmapf(sMinU[r0]) + TAU;
                float thr1 = unmapf(sMinU[r0 + 8]) + TAU;
#pragma unroll
                for (int nf = 0; nf < 4; nf++) {
                    float2 en = *(const float2*)&sEnorm[colB + nf * 8];
                    float d0 = en.x - 2.0f * acc[m][nf][0];
                    float d1 = en.y - 2.0f * acc[m][nf][1];
                    float d2 = en.x - 2.0f * acc[m][nf][2];
                    float d3 = en.y - 2.0f * acc[m][nf][3];
                    int c0 = colB + nf * 8;
                    if (d0 < thr0) { int p = atomicAdd(&sCnt[r0], 1);     if (p < CAP) sCand[r0 * CAP + p] = c0; }
                    if (d1 < thr0) { int p = atomicAdd(&sCnt[r0], 1);     if (p < CAP) sCand[r0 * CAP + p] = c0 + 1; }
                    if (d2 < thr1) { int p = atomicAdd(&sCnt[r0 + 8], 1); if (p < CAP) sCand[(r0 + 8) * CAP + p] = c0; }
                    if (d3 < thr1) { int p = atomicAdd(&sCnt[r0 + 8], 1); if (p < CAP) sCand[(r0 + 8) * CAP + p] = c0 + 1; }
                    acc[m][nf][0] = 0.0f; acc[m][nf][1] = 0.0f;
                    acc[m][nf][2] = 0.0f; acc[m][nf][3] = 0.0f;
                }
            }
        }
        __syncthreads();                                 // stage consumed
        if (tid == 0 && it + 3 < 64) ISSUE(it + 3);
    }

    // dump candidate lists to global (warp w -> rows w*16..w*16+15)
    for (int rr = 0; rr < 16; rr++) {
        int r = wid * 16 + rr;
        int cnt = sCnt[r]; if (cnt > CAP) cnt = CAP;
        if (lane == 0) g_cnt[rowBase + r] = cnt;
        for (int i = lane; i < cnt; i += 32)
            g_cand[(size_t)(rowBase + r) * CAP + i] = sCand[r * CAP + i];
    }
}

// ---------------------------------------------------------------------------
// Refine + output kernel: grid N_TOK/16, 256 threads.
// ---------------------------------------------------------------------------
__global__ __launch_bounds__(256, 8)
void outref_kernel(const float* __restrict__ z, const float* __restrict__ emb,
                   float* __restrict__ out) {
    __shared__ int   sBestC[16];
    __shared__ float sRed[8];
    const int tid  = threadIdx.x;
    const int lane = tid & 31;
    const int wid  = tid >> 5;
    const int rowBase = blockIdx.x * 16;

#pragma unroll
    for (int rr = 0; rr < 2; rr++) {
        int r = rowBase + wid * 2 + rr;
        int cnt = g_cnt[r]; if (cnt > CAP) cnt = CAP;
        const float* zr = z + (size_t)r * DIM;
        float zv[8];
#pragma unroll
        for (int j = 0; j < 8; j++) zv[j] = zr[lane + 32 * j];
        float bestd = 3.4e38f; int bestc = 0;
        for (int i = 0; i < cnt; i++) {
            int c = g_cand[(size_t)r * CAP + i];
            const float* er = emb + (size_t)c * DIM;
            float dot = 0.0f;
#pragma unroll
            for (int j = 0; j < 8; j++) dot += zv[j] * er[lane + 32 * j];
#pragma unroll
            for (int o = 16; o >= 1; o >>= 1) dot += __shfl_xor_sync(0xffffffffu, dot, o);
            float dd = g_enorm[c] - 2.0f * dot;
            if (dd < bestd || (dd == bestd && c < bestc)) { bestd = dd; bestc = c; }
        }
        if (lane == 0) {
            sBestC[wid * 2 + rr] = bestc;
            out[OFF_IDX + r] = (float)bestc;
            atomicAdd(&g_counts[bestc], 1.0f);
        }
    }
    __syncthreads();

    float lossAcc = 0.0f;
    const int d = tid;   // DIM == 256
#pragma unroll
    for (int rr = 0; rr < 16; rr++) {
        int code = sBestC[rr];
        int row  = rowBase + rr;
        float e  = emb[(size_t)code * DIM + d];
        float zvv = z[(size_t)row * DIM + d];
        float diff = e - zvv;
        out[OFF_ZQ + (size_t)row * DIM + d] = zvv + diff;
        lossAcc += diff * diff;
        atomicAdd(&g_esum[code * DIM + d], zvv);
    }
#pragma unroll
    for (int o = 16; o >= 1; o >>= 1) lossAcc += __shfl_xor_sync(0xffffffffu, lossAcc, o);
    if (lane == 0) sRed[wid] = lossAcc;
    __syncthreads();
    if (tid < 8) {
        float v = sRed[tid];
#pragma unroll
        for (int o = 4; o >= 1; o >>= 1) v += __shfl_xor_sync(0xffu, v, o, 8);
        if (tid == 0) atomicAdd(&g_loss, v);
    }
}

// ---------------------------------------------------------------------------
__global__ void fin1_kernel(const float* __restrict__ cs, float* __restrict__ out) {
    int k = threadIdx.x;
    float ncs = cs[k] * 0.99f + 0.01f * g_counts[k];
    out[OFF_CS + k] = ncs;
    __shared__ float red[32];
    float v = ncs;
#pragma unroll
    for (int o = 16; o >= 1; o >>= 1) v += __shfl_xor_sync(0xffffffffu, v, o);
    if ((k & 31) == 0) red[k >> 5] = v;
    __syncthreads();
    if (k < 32) {
        float t = red[k];
#pragma unroll
        for (int o = 16; o >= 1; o >>= 1) t += __shfl_xor_sync(0xffffffffu, t, o);
        if (k == 0) {
            g_nsum = t;
            out[OFF_LOSS] = 0.25f * g_loss / (float)(N_TOK * DIM);
        }
    }
}

__global__ void fin2_kernel(const float* __restrict__ avg, float* __restrict__ out) {
    int i = blockIdx.x * blockDim.x + threadIdx.x;
    float navg = avg[i] * 0.99f + 0.01f * g_esum[i];
    out[OFF_AVG + i] = navg;
    int k = i >> 8;
    float ncs = out[OFF_CS + k];
    float csn = (ncs + 1e-6f) / (g_nsum + (float)NCODE * 1e-6f);
    out[OFF_EMB + i] = navg / csn;
}

// ---------------------------------------------------------------------------
extern "C" void kernel_launch(void* const* d_in, const int* in_sizes, int n_in,
                              void* d_out, int out_size) {
    const float* z   = (const float*)d_in[0];
    const float* emb = (const float*)d_in[1];
    const float* cs  = (const float*)d_in[2];
    const float* avg = (const float*)d_in[3];
    float* out = (float*)d_out;

    cudaFuncSetAttribute(vq_main_kernel,
                         cudaFuncAttributeMaxDynamicSharedMemorySize, SM_TOTAL);

    enorm_kernel<<<(NCODE * 32) / 256, 256>>>(emb);
    prep_kernel<<<(AC + BC + ZC + 255) / 256, 256>>>(z, emb);
    vq_main_kernel<<<N_TOK / 128, 256, SM_TOTAL>>>();
    outref_kernel<<<N_TOK / 16, 256>>>(z, emb, out);
    fin1_kernel<<<1, 1024>>>(cs, out);
    fin2_kernel<<<(NCODE * DIM) / 256, 256>>>(avg, out);
}

// round 9
// speedup vs baseline: 4.9101x; 1.0058x over previous
#include <cuda_runtime.h>
#include <cuda_bf16.h>
#include <cstdint>

#define N_TOK 32768
#define DIM   256
#define NCODE 1024
#define TAU   3.0f
#define CAP   48

// d_out layout (float32): z_q_st, loss, indices, new_cluster_size,
// new_embedding_avg, new_embedding
#define OFF_ZQ   0
#define OFF_LOSS (N_TOK * DIM)
#define OFF_IDX  (OFF_LOSS + 1)
#define OFF_CS   (OFF_IDX + N_TOK)
#define OFF_AVG  (OFF_CS + NCODE)
#define OFF_EMB  (OFF_AVG + NCODE * DIM)

#define TILE_B   10240                   // 128 rows x 80 B (64 B data + pad)

__device__ __align__(16) float g_enorm[NCODE];
__device__ float g_counts[NCODE];
__device__ __align__(16) float g_esum[NCODE * DIM];
__device__ float g_loss;
__device__ float g_nsum;
// tile-contiguous bf16 images: gAt[block][kc][row*80 + c*2], gBt[n][kc][...]
__device__ __align__(16) uint8_t gAt[(N_TOK / 128) * 8 * TILE_B];   // 21 MB
__device__ __align__(16) uint8_t gBt[(NCODE / 128) * 8 * TILE_B];   // 655 KB
__device__ int g_cnt[N_TOK];
__device__ int g_cand[N_TOK * CAP];

// ---------------------------------------------------------------------------
__device__ __forceinline__ uint32_t smem_u32(const void* p) {
    uint32_t a;
    asm("{ .reg .u64 t; cvta.to.shared.u64 t, %1; cvt.u32.u64 %0, t; }"
        : "=r"(a) : "l"(p));
    return a;
}
#define MBAR_INIT(a, c) asm volatile("mbarrier.init.shared.b64 [%0], %1;" \
    :: "r"(a), "r"(c) : "memory")
#define MBAR_EXPECT_TX(a, b) asm volatile(                                    \
    "mbarrier.arrive.expect_tx.shared.b64 _, [%0], %1;"                       \
    :: "r"(a), "r"(b) : "memory")
#define MBAR_WAIT(a, ph) do {                                               \
    uint32_t _m = (a), _p = (ph), _d;                                       \
    asm volatile("{\n\t.reg .pred p;\n\t"                                   \
        "mbarrier.try_wait.parity.acquire.cta.shared::cta.b64 p, [%1], %2;\n\t" \
        "selp.b32 %0, 1, 0, p;\n\t}" : "=r"(_d) : "r"(_m), "r"(_p) : "memory"); \
    if (!_d) {                                                              \
        asm volatile("{\n\t.reg .pred P1;\n\tWL%=:\n\t"                     \
            "mbarrier.try_wait.parity.acquire.cta.shared::cta.b64 P1, [%0], %1, 0x989680;\n\t" \
            "@P1 bra.uni WD%=;\n\tbra.uni WL%=;\n\tWD%=:\n\t}"              \
            :: "r"(_m), "r"(_p) : "memory");                                \
    } } while (0)
#define FENCE_ASYNC() asm volatile("fence.proxy.async.shared::cta;" ::: "memory")

__device__ __forceinline__ void bulk_g2s(uint32_t dst, const void* src,
                                         uint32_t bytes, uint32_t mbar) {
    asm volatile(
        "cp.async.bulk.shared::cta.global.mbarrier::complete_tx::bytes "
        "[%0], [%1], %2, [%3];"
        :: "r"(dst), "l"(__cvta_generic_to_global(src)), "r"(bytes), "r"(mbar)
        : "memory");
}
__device__ __forceinline__ void red_add_v4(float* gptr, float4 v) {
    asm volatile("red.global.add.v4.f32 [%0], {%1, %2, %3, %4};"
                 :: "l"(__cvta_generic_to_global(gptr)),
                    "f"(v.x), "f"(v.y), "f"(v.z), "f"(v.w) : "memory");
}

#define LDSM4(r0, r1, r2, r3, addr) asm volatile(                              \
    "ldmatrix.sync.aligned.m8n8.x4.shared.b16 {%0,%1,%2,%3}, [%4];"            \
    : "=r"(r0), "=r"(r1), "=r"(r2), "=r"(r3) : "r"(addr))

#define MMA(c, a0, a1, a2, a3, b0, b1) asm volatile(                           \
    "mma.sync.aligned.m16n8k16.row.col.f32.bf16.bf16.f32 "                     \
    "{%0,%1,%2,%3},{%4,%5,%6,%7},{%8,%9},{%0,%1,%2,%3};"                       \
    : "+f"((c)[0]), "+f"((c)[1]), "+f"((c)[2]), "+f"((c)[3])                   \
    : "r"(a0), "r"(a1), "r"(a2), "r"(a3), "r"(b0), "r"(b1))

__device__ __forceinline__ unsigned mapf(float d) {
    unsigned u = __float_as_uint(d);
    return (u & 0x80000000u) ? ~u : (u | 0x80000000u);
}
__device__ __forceinline__ float unmapf(unsigned x) {
    return (x & 0x80000000u) ? __uint_as_float(x & 0x7fffffffu)
                             : __uint_as_float(~x);
}

// ---------------------------------------------------------------------------
__global__ void enorm_kernel(const float* __restrict__ emb) {
    int w = (blockIdx.x * blockDim.x + threadIdx.x) >> 5;
    int lane = threadIdx.x & 31;
    if (w >= NCODE) return;
    const float4* p = (const float4*)(emb + (size_t)w * DIM);
    float s = 0.0f;
#pragma unroll
    for (int c = 0; c < 2; c++) {
        float4 v = p[lane + 32 * c];
        s += v.x * v.x + v.y * v.y + v.z * v.z + v.w * v.w;
    }
#pragma unroll
    for (int o = 16; o >= 1; o >>= 1) s += __shfl_xor_sync(0xffffffffu, s, o);
    if (lane == 0) g_enorm[w] = s;
}

// prep: fp32 -> bf16 into tile-contiguous layout; also zeroes scratch.
#define AC (N_TOK * DIM / 8)             // 1,048,576
#define BC (NCODE * DIM / 8)             // 32,768
#define ZC (NCODE * DIM / 4)             // 65,536
__global__ void prep_kernel(const float* __restrict__ z, const float* __restrict__ emb) {
    int p = blockIdx.x * blockDim.x + threadIdx.x;
    if (p < AC) {
        int t = p >> 9, w = p & 511;             // tile, chunk-within
        int row = w >> 2, c4 = w & 3;
        int b = t >> 3, kc = t & 7;
        const float* src = z + (size_t)(b * 128 + row) * DIM + kc * 32 + c4 * 8;
        float4 v0 = *(const float4*)src;
        float4 v1 = *(const float4*)(src + 4);
        __nv_bfloat162 o0 = __halves2bfloat162(__float2bfloat16_rn(v0.x), __float2bfloat16_rn(v0.y));
        __nv_bfloat162 o1 = __halves2bfloat162(__float2bfloat16_rn(v0.z), __float2bfloat16_rn(v0.w));
        __nv_bfloat162 o2 = __halves2bfloat162(__float2bfloat16_rn(v1.x), __float2bfloat16_rn(v1.y));
        __nv_bfloat162 o3 = __halves2bfloat162(__float2bfloat16_rn(v1.z), __float2bfloat16_rn(v1.w));
        uint4 pack = {*(uint32_t*)&o0, *(uint32_t*)&o1, *(uint32_t*)&o2, *(uint32_t*)&o3};
        *(uint4*)(gAt + (size_t)t * TILE_B + row * 80 + c4 * 16) = pack;
    } else if (p < AC + BC) {
        int q = p - AC;
        int t = q >> 9, w = q & 511;
        int row = w >> 2, c4 = w & 3;
        int n = t >> 3, kc = t & 7;
        const float* src = emb + (size_t)(n * 128 + row) * DIM + kc * 32 + c4 * 8;
        float4 v0 = *(const float4*)src;
        float4 v1 = *(const float4*)(src + 4);
        __nv_bfloat162 o0 = __halves2bfloat162(__float2bfloat16_rn(v0.x), __float2bfloat16_rn(v0.y));
        __nv_bfloat162 o1 = __halves2bfloat162(__float2bfloat16_rn(v0.z), __float2bfloat16_rn(v0.w));
        __nv_bfloat162 o2 = __halves2bfloat162(__float2bfloat16_rn(v1.x), __float2bfloat16_rn(v1.y));
        __nv_bfloat162 o3 = __halves2bfloat162(__float2bfloat16_rn(v1.z), __float2bfloat16_rn(v1.w));
        uint4 pack = {*(uint32_t*)&o0, *(uint32_t*)&o1, *(uint32_t*)&o2, *(uint32_t*)&o3};
        *(uint4*)(gBt + (size_t)t * TILE_B + row * 80 + c4 * 16) = pack;
    } else {
        int zi = p - AC - BC;
        if (zi >= ZC) return;
        ((float4*)g_esum)[zi] = make_float4(0.f, 0.f, 0.f, 0.f);
        if (zi < NCODE / 4) ((float4*)g_counts)[zi] = make_float4(0.f, 0.f, 0.f, 0.f);
        if (zi == 0) g_loss = 0.0f;
    }
}

// ---------------------------------------------------------------------------
// Main: bulk-copy-fed bf16 HMMA approx GEMM + windowed candidate collection.
// ---------------------------------------------------------------------------
#define STAGE_SZ 20480                   // A 10240 + B 10240
#define SM_EN    81920                   // 4 KB
#define SM_CAND  86016                   // 128 x CAP x 4 = 24576
#define SM_MINU  110592                  // 128 x u32
#define SM_CNT   111104                  // 128 x int
#define SM_MBAR  111616                  // 4 x 8 B
#define SM_TOTAL 111680

__global__ __launch_bounds__(256, 2)
void vq_main_kernel() {
    extern __shared__ char smem[];
    const uint32_t sb = smem_u32(smem);
    const int tid  = threadIdx.x;
    const int lane = tid & 31;
    const int wid  = tid >> 5;
    const int wm   = wid >> 2;           // 0..1  (M half)
    const int wn   = wid & 3;            // 0..3  (N quarter, 32 cols)
    const int rowBase = blockIdx.x * 128;

    float*    sEnorm = (float*)(smem + SM_EN);
    int*      sCand  = (int*)(smem + SM_CAND);
    unsigned* sMinU  = (unsigned*)(smem + SM_MINU);
    int*      sCnt   = (int*)(smem + SM_CNT);

#pragma unroll
    for (int i = 0; i < 4; i++) sEnorm[tid + i * 256] = g_enorm[tid + i * 256];
    if (tid < 128) { sMinU[tid] = 0xffffffffu; sCnt[tid] = 0; }
    if (tid == 0) {
#pragma unroll
        for (int s = 0; s < 4; s++) MBAR_INIT(sb + SM_MBAR + s * 8, 1);
    }
    __syncthreads();
    FENCE_ASYNC();

    // producer: j = n*8 + kc
#define ISSUE(j) do {                                                          \
    int _s = (j) & 3;                                                          \
    uint32_t _st = sb + _s * STAGE_SZ;                                         \
    uint32_t _mb = sb + SM_MBAR + _s * 8;                                      \
    MBAR_EXPECT_TX(_mb, STAGE_SZ);                                             \
    bulk_g2s(_st, gAt + (size_t)(blockIdx.x * 8 + ((j) & 7)) * TILE_B,         \
             TILE_B, _mb);                                                     \
    bulk_g2s(_st + TILE_B, gBt + (size_t)(j) * TILE_B, TILE_B, _mb);           \
} while (0)

    if (tid == 0) { ISSUE(0); ISSUE(1); ISSUE(2); }

    // ldmatrix per-lane address offsets (bytes), row stride 80B
    const uint32_t aOff = (uint32_t)((wm * 64 + (lane & 15)) * 80 + (lane >> 4) * 16);
    const uint32_t bOff = (uint32_t)((wn * 32 + (lane & 7) + ((lane >> 4) << 3)) * 80
                                     + ((lane >> 3) & 1) * 16);

    float acc[4][4][4];
#pragma unroll
    for (int m = 0; m < 4; m++)
#pragma unroll
        for (int nf = 0; nf < 4; nf++)
#pragma unroll
            for (int v = 0; v < 4; v++) acc[m][nf][v] = 0.0f;

    for (int it = 0; it < 64; it++) {
        MBAR_WAIT(sb + SM_MBAR + (it & 3) * 8, (it >> 2) & 1);

        const uint32_t stBase = sb + (it & 3) * STAGE_SZ;
        const uint32_t aB = stBase + aOff;
        const uint32_t bB = stBase + TILE_B + bOff;

#pragma unroll
        for (int s = 0; s < 2; s++) {                    // two k16 steps
            uint32_t b[4][2];
#pragma unroll
            for (int q = 0; q < 2; q++) {
                uint32_t r0, r1, r2, r3;
                LDSM4(r0, r1, r2, r3, bB + q * 1280 + s * 32);
                b[2 * q][0] = r0; b[2 * q][1] = r1;
                b[2 * q + 1][0] = r2; b[2 * q + 1][1] = r3;
            }
#pragma unroll
            for (int m = 0; m < 4; m++) {
                uint32_t a0, a1, a2, a3;
                LDSM4(a0, a1, a2, a3, aB + m * 1280 + s * 32);
#pragma unroll
                for (int nf = 0; nf < 4; nf++)
                    MMA(acc[m][nf], a0, a1, a2, a3, b[nf][0], b[nf][1]);
            }
        }

        if ((it & 7) == 7) {                             // end of n-tile
            const int n = it >> 3;
            const int colB = n * 128 + wn * 32 + 2 * (lane & 3);
            // pass 1: settle per-row approx min
#pragma unroll
            for (int m = 0; m < 4; m++) {
                int r0 = wm * 64 + m * 16 + (lane >> 2);
                float bd0 = 3.4e38f, bd1 = 3.4e38f;
#pragma unroll
                for (int nf = 0; nf < 4; nf++) {
                    float2 en = *(const float2*)&sEnorm[colB + nf * 8];
                    bd0 = fminf(bd0, fminf(en.x - 2.0f * acc[m][nf][0],
                                           en.y - 2.0f * acc[m][nf][1]));
                    bd1 = fminf(bd1, fminf(en.x - 2.0f * acc[m][nf][2],
                                           en.y - 2.0f * acc[m][nf][3]));
                }
#pragma unroll
                for (int off = 1; off <= 2; off <<= 1) {
                    bd0 = fminf(bd0, __shfl_xor_sync(0xffffffffu, bd0, off));
                    bd1 = fminf(bd1, __shfl_xor_sync(0xffffffffu, bd1, off));
                }
                if ((lane & 3) == 0) {
                    atomicMin(&sMinU[r0], mapf(bd0));
                    atomicMin(&sMinU[r0 + 8], mapf(bd1));
                }
            }
            __syncthreads();
            // pass 2: collect candidates within TAU of settled min
#pragma unroll
            for (int m = 0; m < 4; m++) {
                int r0 = wm * 64 + m * 16 + (lane >> 2);
                float thr0 = unmapf(sMinU[r0]) + TAU;
                float thr1 = unmapf(sMinU[r0 + 8]) + TAU;
#pragma unroll
                for (int nf = 0; nf < 4; nf++) {
                    float2 en = *(const float2*)&sEnorm[colB + nf * 8];
                    float d0 = en.x - 2.0f * acc[m][nf][0];
                    float d1 = en.y - 2.0f * acc[m][nf][1];
                    float d2 = en.x - 2.0f * acc[m][nf][2];
                    float d3 = en.y - 2.0f * acc[m][nf][3];
                    int c0 = colB + nf * 8;
                    if (d0 < thr0) { int p = atomicAdd(&sCnt[r0], 1);     if (p < CAP) sCand[r0 * CAP + p] = c0; }
                    if (d1 < thr0) { int p = atomicAdd(&sCnt[r0], 1);     if (p < CAP) sCand[r0 * CAP + p] = c0 + 1; }
                    if (d2 < thr1) { int p = atomicAdd(&sCnt[r0 + 8], 1); if (p < CAP) sCand[(r0 + 8) * CAP + p] = c0; }
                    if (d3 < thr1) { int p = atomicAdd(&sCnt[r0 + 8], 1); if (p < CAP) sCand[(r0 + 8) * CAP + p] = c0 + 1; }
                    acc[m][nf][0] = 0.0f; acc[m][nf][1] = 0.0f;
                    acc[m][nf][2] = 0.0f; acc[m][nf][3] = 0.0f;
                }
            }
        }
        __syncthreads();                                 // stage consumed
        if (tid == 0 && it + 3 < 64) ISSUE(it + 3);
    }

    // dump candidate lists to global (warp w -> rows w*16..w*16+15)
    for (int rr = 0; rr < 16; rr++) {
        int r = wid * 16 + rr;
        int cnt = sCnt[r]; if (cnt > CAP) cnt = CAP;
        if (lane == 0) g_cnt[rowBase + r] = cnt;
        for (int i = lane; i < cnt; i += 32)
            g_cand[(size_t)(rowBase + r) * CAP + i] = sCand[r * CAP + i];
    }
}

// ---------------------------------------------------------------------------
// Refine + output kernel: grid N_TOK/16, 256 threads.
// Phase A: warp w refines rows (base + w*2, +1) exactly in fp32.
// Phase B: vectorized — thread (rg, c4) owns rows rg*4..rg*4+3, cols c4*4..+3.
//          float4 loads/stores + red.global.add.v4.f32 for esum.
// ---------------------------------------------------------------------------
__global__ __launch_bounds__(256, 8)
void outref_kernel(const float* __restrict__ z, const float* __restrict__ emb,
                   float* __restrict__ out) {
    __shared__ int   sBestC[16];
    __shared__ float sRed[8];
    const int tid  = threadIdx.x;
    const int lane = tid & 31;
    const int wid  = tid >> 5;
    const int rowBase = blockIdx.x * 16;

#pragma unroll
    for (int rr = 0; rr < 2; rr++) {
        int r = rowBase + wid * 2 + rr;
        int cnt = g_cnt[r]; if (cnt > CAP) cnt = CAP;
        const float* zr = z + (size_t)r * DIM;
        float zv[8];
#pragma unroll
        for (int j = 0; j < 8; j++) zv[j] = zr[lane + 32 * j];
        float bestd = 3.4e38f; int bestc = 0;
        for (int i = 0; i < cnt; i++) {
            int c = g_cand[(size_t)r * CAP + i];
            const float* er = emb + (size_t)c * DIM;
            float dot = 0.0f;
#pragma unroll
            for (int j = 0; j < 8; j++) dot += zv[j] * er[lane + 32 * j];
#pragma unroll
            for (int o = 16; o >= 1; o >>= 1) dot += __shfl_xor_sync(0xffffffffu, dot, o);
            float dd = g_enorm[c] - 2.0f * dot;
            if (dd < bestd || (dd == bestd && c < bestc)) { bestd = dd; bestc = c; }
        }
        if (lane == 0) {
            sBestC[wid * 2 + rr] = bestc;
            out[OFF_IDX + r] = (float)bestc;
            atomicAdd(&g_counts[bestc], 1.0f);
        }
    }
    __syncthreads();

    // phase B: 4 row-groups x 64 column-threads, float4 everywhere
    float lossAcc = 0.0f;
    const int c4 = (tid & 63) * 4;
    const int rg = tid >> 6;
#pragma unroll
    for (int k = 0; k < 4; k++) {
        int rr   = rg * 4 + k;
        int code = sBestC[rr];
        int row  = rowBase + rr;
        float4 e  = *(const float4*)(emb + (size_t)code * DIM + c4);
        float4 zv = *(const float4*)(z + (size_t)row * DIM + c4);
        float4 df = make_float4(e.x - zv.x, e.y - zv.y, e.z - zv.z, e.w - zv.w);
        float4 q  = make_float4(zv.x + df.x, zv.y + df.y, zv.z + df.z, zv.w + df.w);
        *(float4*)(out + OFF_ZQ + (size_t)row * DIM + c4) = q;
        lossAcc += df.x * df.x + df.y * df.y + df.z * df.z + df.w * df.w;
        red_add_v4(&g_esum[code * DIM + c4], zv);
    }
#pragma unroll
    for (int o = 16; o >= 1; o >>= 1) lossAcc += __shfl_xor_sync(0xffffffffu, lossAcc, o);
    if (lane == 0) sRed[wid] = lossAcc;
    __syncthreads();
    if (tid < 8) {
        float v = sRed[tid];
#pragma unroll
        for (int o = 4; o >= 1; o >>= 1) v += __shfl_xor_sync(0xffu, v, o, 8);
        if (tid == 0) atomicAdd(&g_loss, v);
    }
}

// ---------------------------------------------------------------------------
__global__ void fin1_kernel(const float* __restrict__ cs, float* __restrict__ out) {
    int k = threadIdx.x;
    float ncs = cs[k] * 0.99f + 0.01f * g_counts[k];
    out[OFF_CS + k] = ncs;
    __shared__ float red[32];
    float v = ncs;
#pragma unroll
    for (int o = 16; o >= 1; o >>= 1) v += __shfl_xor_sync(0xffffffffu, v, o);
    if ((k & 31) == 0) red[k >> 5] = v;
    __syncthreads();
    if (k < 32) {
        float t = red[k];
#pragma unroll
        for (int o = 16; o >= 1; o >>= 1) t += __shfl_xor_sync(0xffffffffu, t, o);
        if (k == 0) {
            g_nsum = t;
            out[OFF_LOSS] = 0.25f * g_loss / (float)(N_TOK * DIM);
        }
    }
}

__global__ void fin2_kernel(const float* __restrict__ avg, float* __restrict__ out) {
    int i = blockIdx.x * blockDim.x + threadIdx.x;
    float navg = avg[i] * 0.99f + 0.01f * g_esum[i];
    out[OFF_AVG + i] = navg;
    int k = i >> 8;
    float ncs = out[OFF_CS + k];
    float csn = (ncs + 1e-6f) / (g_nsum + (float)NCODE * 1e-6f);
    out[OFF_EMB + i] = navg / csn;
}

// ---------------------------------------------------------------------------
extern "C" void kernel_launch(void* const* d_in, const int* in_sizes, int n_in,
                              void* d_out, int out_size) {
    const float* z   = (const float*)d_in[0];
    const float* emb = (const float*)d_in[1];
    const float* cs  = (const float*)d_in[2];
    const float* avg = (const float*)d_in[3];
    float* out = (float*)d_out;

    cudaFuncSetAttribute(vq_main_kernel,
                         cudaFuncAttributeMaxDynamicSharedMemorySize, SM_TOTAL);

    enorm_kernel<<<(NCODE * 32) / 256, 256>>>(emb);
    prep_kernel<<<(AC + BC + ZC + 255) / 256, 256>>>(z, emb);
    vq_main_kernel<<<N_TOK / 128, 256, SM_TOTAL>>>();
    outref_kernel<<<N_TOK / 16, 256>>>(z, emb, out);
    fin1_kernel<<<1, 1024>>>(cs, out);
    fin2_kernel<<<(NCODE * DIM) / 256, 256>>>(avg, out);
}